// round 8
// baseline (speedup 1.0000x reference)
#include <cuda_runtime.h>
#include <cuda_bf16.h>
#include <stdint.h>
#include <math.h>

#define Q_LEN   1024
#define KV_LEN  6404
#define KV_PAD  6464
#define HIDDEN  4096
#define NH      32
#define NKVH    8
#define HD      128
#define QKV_LDB 6144
#define KV_N    2048
#define ATTN_SCALE 0.08838834764831845f
#define INV254  (1.0f / 254.0f)

// ---------------- scratch ----------------
__device__ float g_q[Q_LEN * HIDDEN];
__device__ float g_kv[KV_LEN * KV_N];
__device__ float g_attn[Q_LEN * HIDDEN];

__device__ int8_t g_hid8h[Q_LEN * HIDDEN];
__device__ int8_t g_hid8l[Q_LEN * HIDDEN];
__device__ int8_t g_cross8h[KV_LEN * HIDDEN];
__device__ int8_t g_cross8l[KV_LEN * HIDDEN];
__device__ int8_t g_wq8h[QKV_LDB * HIDDEN];      // [col][k]
__device__ int8_t g_wq8l[QKV_LDB * HIDDEN];
__device__ int8_t g_wo8h[HIDDEN * HIDDEN];
__device__ int8_t g_wo8l[HIDDEN * HIDDEN];
__device__ int8_t g_attn8h[Q_LEN * HIDDEN];
__device__ int8_t g_attn8l[Q_LEN * HIDDEN];
__device__ int8_t g_q8h[Q_LEN * HIDDEN];
__device__ int8_t g_q8l[Q_LEN * HIDDEN];
__device__ int8_t g_k8h[KV_LEN * (NKVH * HD)];
__device__ int8_t g_k8l[KV_LEN * (NKVH * HD)];

__device__ __nv_bfloat16 g_vthi[NKVH * HD * KV_PAD];
__device__ __nv_bfloat16 g_vtlo[NKVH * HD * KV_PAD];

__device__ float g_s_hid[Q_LEN];
__device__ float g_s_cross[KV_LEN];
__device__ float g_s_attn[Q_LEN];
__device__ float g_sbq[QKV_LDB];
__device__ float g_sbq_inv[QKV_LDB];
__device__ float g_sbo[HIDDEN];
__device__ float g_sbo_inv[HIDDEN];
__device__ float g_sq[Q_LEN * NH];
__device__ float g_sk[KV_LEN * NKVH];

// ---------------- helpers ----------------
__device__ __forceinline__ uint32_t smem_u32(const void* p)
{
    uint32_t a;
    asm("{ .reg .u64 t; cvta.to.shared.u64 t, %1; cvt.u32.u64 %0, t; }"
        : "=r"(a) : "l"(p));
    return a;
}
#define CP16(dst, src, n) \
    asm volatile("cp.async.cg.shared.global [%0], [%1], 16, %2;" \
                 :: "r"(dst), "l"(src), "r"(n))
#define CP_COMMIT() asm volatile("cp.async.commit_group;" ::: "memory")
#define CP_WAIT0()  asm volatile("cp.async.wait_group 0;" ::: "memory")

#define IMMA(d, a, b)                                                          \
    asm volatile(                                                              \
        "mma.sync.aligned.m16n8k32.row.col.s32.s8.s8.s32 "                     \
        "{%0,%1,%2,%3},{%4,%5,%6,%7},{%8,%9},{%0,%1,%2,%3};"                   \
        : "+r"((d)[0]), "+r"((d)[1]), "+r"((d)[2]), "+r"((d)[3])               \
        : "r"((a)[0]), "r"((a)[1]), "r"((a)[2]), "r"((a)[3]),                  \
          "r"((b)[0]), "r"((b)[1]))

#define MMA_BF16(d, a, b)                                                      \
    asm volatile(                                                              \
        "mma.sync.aligned.m16n8k16.row.col.f32.bf16.bf16.f32 "                 \
        "{%0,%1,%2,%3},{%4,%5,%6,%7},{%8,%9},{%0,%1,%2,%3};"                   \
        : "+f"((d)[0]), "+f"((d)[1]), "+f"((d)[2]), "+f"((d)[3])               \
        : "r"((a)[0]), "r"((a)[1]), "r"((a)[2]), "r"((a)[3]),                  \
          "r"((b)[0]), "r"((b)[1]))

__device__ __forceinline__ void split2(float x, float y, unsigned& hi, unsigned& lo)
{
    __nv_bfloat16 hx = __float2bfloat16(x), hy = __float2bfloat16(y);
    float lx = x - __bfloat162float(hx), ly = y - __bfloat162float(hy);
    __nv_bfloat16 lxb = __float2bfloat16(lx), lyb = __float2bfloat16(ly);
    hi = (unsigned)__bfloat16_as_ushort(hx) | ((unsigned)__bfloat16_as_ushort(hy) << 16);
    lo = (unsigned)__bfloat16_as_ushort(lxb) | ((unsigned)__bfloat16_as_ushort(lyb) << 16);
}

__device__ __forceinline__ int8_t q8(float v, float inv, int& l)
{
    int h = __float2int_rn(v * inv);
    h = max(-127, min(127, h));
    float r = v * inv - (float)h;
    l = __float2int_rn(r * 254.0f);
    l = max(-127, min(127, l));
    return (int8_t)h;
}

// ---------------- per-row quantization (K = 4096), one block/row -------------
__global__ void __launch_bounds__(256) quant_rows(
    const float* __restrict__ x, int8_t* __restrict__ h8,
    int8_t* __restrict__ l8, float* __restrict__ sc)
{
    __shared__ float red[8];
    const int row = blockIdx.x, tid = threadIdx.x;
    const float* p = x + (size_t)row * HIDDEN;
    float v[16];
#pragma unroll
    for (int i = 0; i < 4; i++)
        *(float4*)&v[i * 4] = *(const float4*)(p + tid * 16 + i * 4);
    float m = 0.f;
#pragma unroll
    for (int i = 0; i < 16; i++) m = fmaxf(m, fabsf(v[i]));
#pragma unroll
    for (int o = 16; o > 0; o >>= 1) m = fmaxf(m, __shfl_xor_sync(0xffffffffu, m, o));
    if ((tid & 31) == 0) red[tid >> 5] = m;
    __syncthreads();
    m = red[0];
#pragma unroll
    for (int i = 1; i < 8; i++) m = fmaxf(m, red[i]);
    m = fmaxf(m, 1e-30f);
    const float inv = 127.f / m;
    if (tid == 0) sc[row] = m * (1.f / 127.f);
#pragma unroll
    for (int i = 0; i < 4; i++) {
        int l0, l1, l2, l3;
        char4 hc, lc;
        hc.x = q8(v[i * 4 + 0], inv, l0);
        hc.y = q8(v[i * 4 + 1], inv, l1);
        hc.z = q8(v[i * 4 + 2], inv, l2);
        hc.w = q8(v[i * 4 + 3], inv, l3);
        lc.x = (int8_t)l0; lc.y = (int8_t)l1; lc.z = (int8_t)l2; lc.w = (int8_t)l3;
        size_t off = (size_t)row * HIDDEN + tid * 16 + i * 4;
        *(char4*)(h8 + off) = hc;
        *(char4*)(l8 + off) = lc;
    }
}

// ---------------- per-column |max| of w [R][C] --------------------------------
__global__ void colmax_kernel(const float* __restrict__ w, float* __restrict__ sb,
                              float* __restrict__ sbinv, int R, int C)
{
    __shared__ float red[8][32];
    const int tx = threadIdx.x, ty = threadIdx.y;
    const int c = blockIdx.x * 32 + tx;
    float m = 0.f;
    for (int r = ty; r < R; r += 8)
        m = fmaxf(m, fabsf(w[(size_t)r * C + c]));
    red[ty][tx] = m;
    __syncthreads();
    if (ty == 0) {
#pragma unroll
        for (int i = 1; i < 8; i++) m = fmaxf(m, red[i][tx]);
        m = fmaxf(m, 1e-30f);
        sb[c] = m * (1.f / 127.f);
        sbinv[c] = 127.f / m;
    }
}

// ---------------- transpose + quantize weights: [R][C] -> int8 [C][R] --------
__global__ void wtrans_quant(const float* __restrict__ w, int8_t* __restrict__ h8,
                             int8_t* __restrict__ l8, const float* __restrict__ sbinv,
                             int R, int C)
{
    __shared__ float t[32][33];
    const int tx = threadIdx.x, ty = threadIdx.y;
    const int r0 = blockIdx.y * 32, c0 = blockIdx.x * 32;
#pragma unroll
    for (int i = 0; i < 4; i++)
        t[ty + 8 * i][tx] = w[(size_t)(r0 + ty + 8 * i) * C + c0 + tx];
    __syncthreads();
#pragma unroll
    for (int i = 0; i < 4; i++) {
        float v = t[tx][ty + 8 * i];
        int cc = c0 + ty + 8 * i;
        float inv = sbinv[cc];
        int l;
        int8_t h = q8(v, inv, l);
        size_t off = (size_t)cc * R + r0 + tx;
        h8[off] = h;
        l8[off] = (int8_t)l;
    }
}

// ---------------- V transpose + bf16 split ----------------
__global__ void vtrans_split(const float* __restrict__ kv)
{
    __shared__ float t[32][33];
    int tx = threadIdx.x, ty = threadIdx.y;
    int kv0 = blockIdx.x * 32, d0 = blockIdx.y * 32, kvh = blockIdx.z;
#pragma unroll
    for (int i = 0; i < 4; i++) {
        int r = kv0 + ty + 8 * i;
        t[ty + 8 * i][tx] = (r < KV_LEN)
            ? kv[(size_t)r * KV_N + NKVH * HD + kvh * HD + d0 + tx] : 0.f;
    }
    __syncthreads();
#pragma unroll
    for (int i = 0; i < 4; i++) {
        float v = t[tx][ty + 8 * i];
        __nv_bfloat16 hb = __float2bfloat16(v);
        __nv_bfloat16 lb = __float2bfloat16(v - __bfloat162float(hb));
        size_t off = (size_t)(kvh * HD + d0 + ty + 8 * i) * KV_PAD + kv0 + tx;
        g_vthi[off] = hb; g_vtlo[off] = lb;
    }
}

// ---------------- RMS norm -> int8 hi/lo + scale, one warp/(row,head) --------
__global__ void rmsnorm_quant(const float* __restrict__ x, const float* __restrict__ w,
                              int8_t* __restrict__ h8, int8_t* __restrict__ l8,
                              float* __restrict__ sc,
                              int nrows, int nheads, int ld_in, int ld_out)
{
    int gw = (int)((blockIdx.x * blockDim.x + threadIdx.x) >> 5);
    int lane = threadIdx.x & 31;
    if (gw >= nrows * nheads) return;
    int row = gw / nheads, h = gw - row * nheads;
    const float* p = x + (size_t)row * ld_in + h * HD;
    float4 v = *(const float4*)(p + lane * 4);
    float ss = v.x * v.x + v.y * v.y + v.z * v.z + v.w * v.w;
#pragma unroll
    for (int o = 16; o > 0; o >>= 1) ss += __shfl_xor_sync(0xffffffffu, ss, o);
    float s = rsqrtf(ss * (1.f / HD) + 1e-5f);
    float4 wv = *(const float4*)(w + lane * 4);
    v.x *= s * wv.x; v.y *= s * wv.y; v.z *= s * wv.z; v.w *= s * wv.w;
    float m = fmaxf(fmaxf(fabsf(v.x), fabsf(v.y)), fmaxf(fabsf(v.z), fabsf(v.w)));
#pragma unroll
    for (int o = 16; o > 0; o >>= 1) m = fmaxf(m, __shfl_xor_sync(0xffffffffu, m, o));
    m = fmaxf(m, 1e-30f);
    float inv = 127.f / m;
    int l0, l1, l2, l3;
    char4 hc, lc;
    hc.x = q8(v.x, inv, l0); hc.y = q8(v.y, inv, l1);
    hc.z = q8(v.z, inv, l2); hc.w = q8(v.w, inv, l3);
    lc.x = (int8_t)l0; lc.y = (int8_t)l1; lc.z = (int8_t)l2; lc.w = (int8_t)l3;
    size_t off = (size_t)row * ld_out + h * HD + lane * 4;
    *(char4*)(h8 + off) = hc;
    *(char4*)(l8 + off) = lc;
    if (lane == 0) sc[gw] = m * (1.f / 127.f);
}

// ---------------- int8x2 IMMA GEMM: C[M,N] = diag(sa) (Ah+Al/254)(Bh+Bl/254)^T diag(sb)
// block 128x128, BK=64, 256 threads (8 warps, 2m x 4n, warp tile 64x32), K=4096.
#define GQ_ST    80
#define GQ_BUF   (128 * GQ_ST)
#define GQ_STAGE (4 * GQ_BUF)
#define GQ_SMEM  (2 * GQ_STAGE)

__global__ void __launch_bounds__(256, 1) gemm_imma(
    const int8_t* __restrict__ Ah8, const int8_t* __restrict__ Al8,
    const int8_t* __restrict__ Bh8, const int8_t* __restrict__ Bl8,
    const float* __restrict__ sa, const float* __restrict__ sbc,
    float* __restrict__ C, int M, int ldc)
{
    extern __shared__ char smg[];
    const uint32_t sb = smem_u32(smg);
    const int tid = threadIdx.x;
    const int warp = tid >> 5, lane = tid & 31;
    const int g = lane >> 2, tig = lane & 3;
    const int wm = warp & 1, wn = warp >> 1;     // 2 x 4
    const int row0 = blockIdx.y * 128, col0 = blockIdx.x * 128;
    const int K = HIDDEN;
    const int nck = K / 64;

    int acc_h[4][4][4], acc_c[4][4][4];
#pragma unroll
    for (int i = 0; i < 4; i++)
#pragma unroll
        for (int j = 0; j < 4; j++)
#pragma unroll
            for (int t = 0; t < 4; t++) { acc_h[i][j][t] = 0; acc_c[i][j][t] = 0; }

    // ---- loader: fill stage st with chunk ck ----
    auto load_chunk = [&](int ck, int st) {
        const uint32_t stb = sb + st * GQ_STAGE;
        const int k0 = ck * 64;
#pragma unroll
        for (int i = 0; i < 2; i++) {
            int idx = tid + i * 256;
            int r = idx >> 2, c = idx & 3;
            uint32_t soff = (uint32_t)(r * GQ_ST + c * 16);
            int gr = row0 + r;
            int ok = (gr < M) ? 16 : 0;
            int grc = (gr < M) ? gr : (M - 1);
            size_t aoff = (size_t)grc * K + k0 + c * 16;
            CP16(stb + 0 * GQ_BUF + soff, Ah8 + aoff, ok);
            CP16(stb + 1 * GQ_BUF + soff, Al8 + aoff, ok);
            size_t boff = (size_t)(col0 + r) * K + k0 + c * 16;
            CP16(stb + 2 * GQ_BUF + soff, Bh8 + boff, 16);
            CP16(stb + 3 * GQ_BUF + soff, Bl8 + boff, 16);
        }
    };

    load_chunk(0, 0);
    CP_COMMIT();

    for (int ck = 0; ck < nck; ck++) {
        const int st = ck & 1;
        CP_WAIT0();
        __syncthreads();
        if (ck + 1 < nck) {
            load_chunk(ck + 1, st ^ 1);
            CP_COMMIT();
        }
        const uint32_t stb = sb + st * GQ_STAGE;
        const char* sm = smg + (size_t)st * GQ_STAGE;
#pragma unroll
        for (int ks = 0; ks < 2; ks++) {
            unsigned ah[4][4], al[4][4], bh[4][2], bl[4][2];
#pragma unroll
            for (int mt = 0; mt < 4; mt++) {
                int rr = wm * 64 + mt * 16 + g;
                int base = rr * GQ_ST + ks * 32 + 4 * tig;
                ah[mt][0] = *(const unsigned*)(sm + 0 * GQ_BUF + base);
                ah[mt][1] = *(const unsigned*)(sm + 0 * GQ_BUF + base + 8 * GQ_ST);
                ah[mt][2] = *(const unsigned*)(sm + 0 * GQ_BUF + base + 16);
                ah[mt][3] = *(const unsigned*)(sm + 0 * GQ_BUF + base + 8 * GQ_ST + 16);
                al[mt][0] = *(const unsigned*)(sm + 1 * GQ_BUF + base);
                al[mt][1] = *(const unsigned*)(sm + 1 * GQ_BUF + base + 8 * GQ_ST);
                al[mt][2] = *(const unsigned*)(sm + 1 * GQ_BUF + base + 16);
                al[mt][3] = *(const unsigned*)(sm + 1 * GQ_BUF + base + 8 * GQ_ST + 16);
            }
#pragma unroll
            for (int nt = 0; nt < 4; nt++) {
                int cc = wn * 32 + nt * 8 + g;
                int base = cc * GQ_ST + ks * 32 + 4 * tig;
                bh[nt][0] = *(const unsigned*)(sm + 2 * GQ_BUF + base);
                bh[nt][1] = *(const unsigned*)(sm + 2 * GQ_BUF + base + 16);
                bl[nt][0] = *(const unsigned*)(sm + 3 * GQ_BUF + base);
                bl[nt][1] = *(const unsigned*)(sm + 3 * GQ_BUF + base + 16);
            }
#pragma unroll
            for (int mt = 0; mt < 4; mt++)
#pragma unroll
                for (int nt = 0; nt < 4; nt++) {
                    IMMA(acc_h[mt][nt], ah[mt], bh[nt]);
                    IMMA(acc_c[mt][nt], ah[mt], bl[nt]);
                    IMMA(acc_c[mt][nt], al[mt], bh[nt]);
                }
        }
        __syncthreads();
        (void)stb;
    }

    // ---- epilogue ----
#pragma unroll
    for (int mt = 0; mt < 4; mt++) {
#pragma unroll
        for (int nt = 0; nt < 4; nt++) {
            int r = row0 + wm * 64 + mt * 16 + g;
            int c = col0 + wn * 32 + nt * 8 + tig * 2;
            float2 sbv = *(const float2*)(sbc + c);
            if (r < M) {
                float s0 = sa[r];
                float v0 = ((float)acc_h[mt][nt][0] + (float)acc_c[mt][nt][0] * INV254)
                           * s0 * sbv.x;
                float v1 = ((float)acc_h[mt][nt][1] + (float)acc_c[mt][nt][1] * INV254)
                           * s0 * sbv.y;
                *(float2*)(C + (size_t)r * ldc + c) = make_float2(v0, v1);
            }
            if (r + 8 < M) {
                float s1 = sa[r + 8];
                float v2 = ((float)acc_h[mt][nt][2] + (float)acc_c[mt][nt][2] * INV254)
                           * s1 * sbv.x;
                float v3 = ((float)acc_h[mt][nt][3] + (float)acc_c[mt][nt][3] * INV254)
                           * s1 * sbv.y;
                *(float2*)(C + (size_t)(r + 8) * ldc + c) = make_float2(v2, v3);
            }
        }
    }
}

// ---------------- flash attention: int8 IMMA QK^T + bf16x3 PV -----------------
// grid (8 q-tiles of 128, 32 heads), 256 threads (8 warps x 16 q-rows).
#define AQST 144
#define AVST 72
#define AQH 0
#define AQL (128 * AQST)
#define AKH (2 * 128 * AQST)
#define AKL (AKH + 64 * AQST)
#define AVH (AKL + 64 * AQST)
#define AVL (AVH + 128 * AVST * 2)
#define ASK (AVL + 128 * AVST * 2)
#define ATTN_SMEM (ASK + 256)

__global__ void __launch_bounds__(256, 1) attn_mma(const float* __restrict__ mask)
{
    extern __shared__ char sma[];
    const int tid = threadIdx.x, warp = tid >> 5, lane = tid & 31;
    const int g = lane >> 2, tig = lane & 3;
    const int h = blockIdx.y, kvh = h >> 2;
    const int q0 = blockIdx.x * 128;
    const int wr = warp * 16;
    const int row0 = q0 + wr + g;
    float* SK = (float*)(sma + ASK);
    __nv_bfloat16* Vh = (__nv_bfloat16*)(sma + AVH);
    __nv_bfloat16* Vl = (__nv_bfloat16*)(sma + AVL);

    // Q int8 tiles resident: 128 rows x 128 bytes (hi & lo)
#pragma unroll
    for (int it = 0; it < 4; it++) {
        int idx = tid + it * 256;
        int r = idx >> 3, c = (idx & 7) * 16;
        size_t off = (size_t)(q0 + r) * HIDDEN + h * HD + c;
        *(uint4*)(sma + AQH + r * AQST + c) = *(const uint4*)(g_q8h + off);
        *(uint4*)(sma + AQL + r * AQST + c) = *(const uint4*)(g_q8l + off);
    }
    const float cf0 = g_sq[(size_t)row0 * NH + h] * ATTN_SCALE;
    const float cf1 = g_sq[(size_t)(row0 + 8) * NH + h] * ATTN_SCALE;

    float o[16][4];
#pragma unroll
    for (int n = 0; n < 16; n++)
#pragma unroll
        for (int t = 0; t < 4; t++) o[n][t] = 0.f;
    float m0 = -1e30f, m1 = -1e30f, l0 = 0.f, l1 = 0.f;

    for (int kv0 = 0; kv0 < KV_LEN; kv0 += 64) {
        __syncthreads();
        // K int8 tiles: 64 rows x 128 bytes
#pragma unroll
        for (int it = 0; it < 2; it++) {
            int idx = tid + it * 256;
            int r = idx >> 3, c = (idx & 7) * 16;
            uint4 vh = make_uint4(0, 0, 0, 0), vl = vh;
            if (kv0 + r < KV_LEN) {
                size_t off = (size_t)(kv0 + r) * (NKVH * HD) + kvh * HD + c;
                vh = *(const uint4*)(g_k8h + off);
                vl = *(const uint4*)(g_k8l + off);
            }
            *(uint4*)(sma + AKH + r * AQST + c) = vh;
            *(uint4*)(sma + AKL + r * AQST + c) = vl;
        }
        // V bf16 tiles: [d][kv] 128 x 64
#pragma unroll
        for (int it = 0; it < 4; it++) {
            int idx = tid + it * 256;
            int d = idx >> 3, c = (idx & 7) * 8;
            size_t off = ((size_t)kvh * HD + d) * KV_PAD + kv0 + c;
            *(uint4*)&Vh[d * AVST + c] = *(const uint4*)(g_vthi + off);
            *(uint4*)&Vl[d * AVST + c] = *(const uint4*)(g_vtlo + off);
        }
        if (tid < 64)
            SK[tid] = (kv0 + tid < KV_LEN)
                    ? g_sk[(size_t)(kv0 + tid) * NKVH + kvh] : 0.f;
        __syncthreads();

        // ---- S = Q K^T via int8 IMMA ----
        int sh[8][4], scr[8][4];
#pragma unroll
        for (int j = 0; j < 8; j++)
#pragma unroll
            for (int c = 0; c < 4; c++) { sh[j][c] = 0; scr[j][c] = 0; }

#pragma unroll
        for (int ks = 0; ks < 4; ks++) {
            int ab = (wr + g) * AQST + ks * 32 + 4 * tig;
            unsigned ah[4], al[4];
            ah[0] = *(const unsigned*)(sma + AQH + ab);
            ah[1] = *(const unsigned*)(sma + AQH + ab + 8 * AQST);
            ah[2] = *(const unsigned*)(sma + AQH + ab + 16);
            ah[3] = *(const unsigned*)(sma + AQH + ab + 8 * AQST + 16);
            al[0] = *(const unsigned*)(sma + AQL + ab);
            al[1] = *(const unsigned*)(sma + AQL + ab + 8 * AQST);
            al[2] = *(const unsigned*)(sma + AQL + ab + 16);
            al[3] = *(const unsigned*)(sma + AQL + ab + 8 * AQST + 16);
#pragma unroll
            for (int j = 0; j < 8; j++) {
                int bb = (8 * j + g) * AQST + ks * 32 + 4 * tig;
                unsigned bh[2], bl[2];
                bh[0] = *(const unsigned*)(sma + AKH + bb);
                bh[1] = *(const unsigned*)(sma + AKH + bb + 16);
                bl[0] = *(const unsigned*)(sma + AKL + bb);
                bl[1] = *(const unsigned*)(sma + AKL + bb + 16);
                IMMA(sh[j], ah, bh);
                IMMA(scr[j], ah, bl);
                IMMA(scr[j], al, bh);
            }
        }

        // ---- dequant + scale + mask ----
        float s[8][4];
        bool partial = (kv0 + 64 > KV_LEN);
        float rmax0 = -1e30f, rmax1 = -1e30f;
        if (!partial) {
#pragma unroll
            for (int j = 0; j < 8; j++) {
                int col = kv0 + 8 * j + tig * 2;
                float sk0 = SK[8 * j + tig * 2], sk1 = SK[8 * j + tig * 2 + 1];
                const float* mp = mask + (size_t)row0 * KV_LEN + col;
                float2 mk0 = *(const float2*)mp;
                float2 mk1 = *(const float2*)(mp + (size_t)8 * KV_LEN);
                float a0 = (float)sh[j][0] + (float)scr[j][0] * INV254;
                float a1 = (float)sh[j][1] + (float)scr[j][1] * INV254;
                float a2 = (float)sh[j][2] + (float)scr[j][2] * INV254;
                float a3 = (float)sh[j][3] + (float)scr[j][3] * INV254;
                s[j][0] = fmaf(a0, cf0 * sk0, mk0.x);
                s[j][1] = fmaf(a1, cf0 * sk1, mk0.y);
                s[j][2] = fmaf(a2, cf1 * sk0, mk1.x);
                s[j][3] = fmaf(a3, cf1 * sk1, mk1.y);
                rmax0 = fmaxf(rmax0, fmaxf(s[j][0], s[j][1]));
                rmax1 = fmaxf(rmax1, fmaxf(s[j][2], s[j][3]));
            }
        } else {
#pragma unroll
            for (int j = 0; j < 8; j++) {
#pragma unroll
                for (int c = 0; c < 2; c++) {
                    int col = kv0 + 8 * j + tig * 2 + c;
                    if (col < KV_LEN) {
                        float sk = SK[8 * j + tig * 2 + c];
                        float a0 = (float)sh[j][c] + (float)scr[j][c] * INV254;
                        float a2 = (float)sh[j][2 + c] + (float)scr[j][2 + c] * INV254;
                        s[j][c]     = fmaf(a0, cf0 * sk,
                                           mask[(size_t)row0 * KV_LEN + col]);
                        s[j][2 + c] = fmaf(a2, cf1 * sk,
                                           mask[(size_t)(row0 + 8) * KV_LEN + col]);
                    } else {
                        s[j][c] = -1e30f;
                        s[j][2 + c] = -1e30f;
                    }
                }
                rmax0 = fmaxf(rmax0, fmaxf(s[j][0], s[j][1]));
                rmax1 = fmaxf(rmax1, fmaxf(s[j][2], s[j][3]));
            }
        }
        rmax0 = fmaxf(rmax0, __shfl_xor_sync(0xffffffffu, rmax0, 1));
        rmax0 = fmaxf(rmax0, __shfl_xor_sync(0xffffffffu, rmax0, 2));
        rmax1 = fmaxf(rmax1, __shfl_xor_sync(0xffffffffu, rmax1, 1));
        rmax1 = fmaxf(rmax1, __shfl_xor_sync(0xffffffffu, rmax1, 2));

        float mn0 = fmaxf(m0, rmax0), mn1 = fmaxf(m1, rmax1);
        float f0 = __expf(m0 - mn0), f1 = __expf(m1 - mn1);
        m0 = mn0; m1 = mn1;

        float sum0 = 0.f, sum1 = 0.f;
#pragma unroll
        for (int j = 0; j < 8; j++) {
            s[j][0] = __expf(s[j][0] - mn0);
            s[j][1] = __expf(s[j][1] - mn0);
            s[j][2] = __expf(s[j][2] - mn1);
            s[j][3] = __expf(s[j][3] - mn1);
            sum0 += s[j][0] + s[j][1];
            sum1 += s[j][2] + s[j][3];
        }
        sum0 += __shfl_xor_sync(0xffffffffu, sum0, 1);
        sum0 += __shfl_xor_sync(0xffffffffu, sum0, 2);
        sum1 += __shfl_xor_sync(0xffffffffu, sum1, 1);
        sum1 += __shfl_xor_sync(0xffffffffu, sum1, 2);
        l0 = l0 * f0 + sum0;
        l1 = l1 * f1 + sum1;

#pragma unroll
        for (int n = 0; n < 16; n++) {
            o[n][0] *= f0; o[n][1] *= f0; o[n][2] *= f1; o[n][3] *= f1;
        }

        // ---- PV (bf16x3; P fragments from s registers) ----
#pragma unroll
        for (int t = 0; t < 4; t++) {
            unsigned ph[4], pl[4];
            split2(s[2 * t][0],     s[2 * t][1],     ph[0], pl[0]);
            split2(s[2 * t][2],     s[2 * t][3],     ph[1], pl[1]);
            split2(s[2 * t + 1][0], s[2 * t + 1][1], ph[2], pl[2]);
            split2(s[2 * t + 1][2], s[2 * t + 1][3], ph[3], pl[3]);
#pragma unroll
            for (int n = 0; n < 16; n++) {
                int vb = (8 * n + g) * AVST + t * 16 + tig * 2;
                unsigned bh[2], bl[2];
                bh[0] = *(const unsigned*)&Vh[vb];
                bh[1] = *(const unsigned*)&Vh[vb + 8];
                bl[0] = *(const unsigned*)&Vl[vb];
                bl[1] = *(const unsigned*)&Vl[vb + 8];
                MMA_BF16(o[n], ph, bh);
                MMA_BF16(o[n], pl, bh);
                MMA_BF16(o[n], ph, bl);
            }
        }
    }

    // ---- epilogue: fp32 to g_attn ----
    float il0 = 1.f / l0, il1 = 1.f / l1;
#pragma unroll
    for (int n = 0; n < 16; n++) {
        size_t base = (size_t)row0 * HIDDEN + h * HD + 8 * n + tig * 2;
        *(float2*)(g_attn + base) = make_float2(o[n][0] * il0, o[n][1] * il0);
        *(float2*)(g_attn + base + (size_t)8 * HIDDEN) =
            make_float2(o[n][2] * il1, o[n][3] * il1);
    }
}

// ---------------------------------------------------------------------------
extern "C" void kernel_launch(void* const* d_in, const int* in_sizes, int n_in,
                              void* d_out, int out_size)
{
    const float* hidden = (const float*)d_in[0];
    const float* cross  = (const float*)d_in[1];
    const float* mask   = (const float*)d_in[2];
    const float* w_qkv  = (const float*)d_in[3];
    const float* w_o    = (const float*)d_in[4];
    const float* q_norm = (const float*)d_in[5];
    const float* k_norm = (const float*)d_in[6];
    float* out = (float*)d_out;
    (void)in_sizes; (void)n_in; (void)out_size;

    float *pq, *pkv, *pattn;
    cudaGetSymbolAddress((void**)&pq,    g_q);
    cudaGetSymbolAddress((void**)&pkv,   g_kv);
    cudaGetSymbolAddress((void**)&pattn, g_attn);
    int8_t *hid8h, *hid8l, *cross8h, *cross8l, *wq8h, *wq8l, *wo8h, *wo8l;
    int8_t *attn8h, *attn8l, *q8hp, *q8lp, *k8hp, *k8lp;
    float *s_hid, *s_cross, *s_attn, *sbq, *sbq_inv, *sbo, *sbo_inv, *sqp, *skp;
    cudaGetSymbolAddress((void**)&hid8h,   g_hid8h);
    cudaGetSymbolAddress((void**)&hid8l,   g_hid8l);
    cudaGetSymbolAddress((void**)&cross8h, g_cross8h);
    cudaGetSymbolAddress((void**)&cross8l, g_cross8l);
    cudaGetSymbolAddress((void**)&wq8h,    g_wq8h);
    cudaGetSymbolAddress((void**)&wq8l,    g_wq8l);
    cudaGetSymbolAddress((void**)&wo8h,    g_wo8h);
    cudaGetSymbolAddress((void**)&wo8l,    g_wo8l);
    cudaGetSymbolAddress((void**)&attn8h,  g_attn8h);
    cudaGetSymbolAddress((void**)&attn8l,  g_attn8l);
    cudaGetSymbolAddress((void**)&q8hp,    g_q8h);
    cudaGetSymbolAddress((void**)&q8lp,    g_q8l);
    cudaGetSymbolAddress((void**)&k8hp,    g_k8h);
    cudaGetSymbolAddress((void**)&k8lp,    g_k8l);
    cudaGetSymbolAddress((void**)&s_hid,   g_s_hid);
    cudaGetSymbolAddress((void**)&s_cross, g_s_cross);
    cudaGetSymbolAddress((void**)&s_attn,  g_s_attn);
    cudaGetSymbolAddress((void**)&sbq,     g_sbq);
    cudaGetSymbolAddress((void**)&sbq_inv, g_sbq_inv);
    cudaGetSymbolAddress((void**)&sbo,     g_sbo);
    cudaGetSymbolAddress((void**)&sbo_inv, g_sbo_inv);
    cudaGetSymbolAddress((void**)&sqp,     g_sq);
    cudaGetSymbolAddress((void**)&skp,     g_sk);

    // activation quantization
    quant_rows<<<Q_LEN, 256>>>(hidden, hid8h, hid8l, s_hid);
    quant_rows<<<KV_LEN, 256>>>(cross, cross8h, cross8l, s_cross);

    // weight col scales + transpose-quant
    colmax_kernel<<<QKV_LDB / 32, dim3(32, 8)>>>(w_qkv, sbq, sbq_inv, HIDDEN, QKV_LDB);
    colmax_kernel<<<HIDDEN / 32, dim3(32, 8)>>>(w_o, sbo, sbo_inv, HIDDEN, HIDDEN);
    wtrans_quant<<<dim3(QKV_LDB / 32, HIDDEN / 32), dim3(32, 8)>>>(
        w_qkv, wq8h, wq8l, sbq_inv, HIDDEN, QKV_LDB);
    wtrans_quant<<<dim3(HIDDEN / 32, HIDDEN / 32), dim3(32, 8)>>>(
        w_o, wo8h, wo8l, sbo_inv, HIDDEN, HIDDEN);

    cudaFuncSetAttribute(gemm_imma, cudaFuncAttributeMaxDynamicSharedMemorySize,
                         GQ_SMEM);
    // Q projection: M=1024, N=4096
    gemm_imma<<<dim3(HIDDEN / 128, Q_LEN / 128), 256, GQ_SMEM>>>(
        hid8h, hid8l, wq8h, wq8l, s_hid, sbq, pq, Q_LEN, HIDDEN);
    // KV projection: M=6404, N=2048 (wqkvT rows 4096..6143)
    gemm_imma<<<dim3(KV_N / 128, (KV_LEN + 127) / 128), 256, GQ_SMEM>>>(
        cross8h, cross8l,
        wq8h + (size_t)(NH * HD) * HIDDEN, wq8l + (size_t)(NH * HD) * HIDDEN,
        s_cross, sbq + NH * HD, pkv, KV_LEN, KV_N);

    // RMS norms -> int8 + scale
    {
        int nwarps = Q_LEN * NH;
        rmsnorm_quant<<<(nwarps * 32 + 255) / 256, 256>>>(
            pq, q_norm, q8hp, q8lp, sqp, Q_LEN, NH, HIDDEN, HIDDEN);
        nwarps = KV_LEN * NKVH;
        rmsnorm_quant<<<(nwarps * 32 + 255) / 256, 256>>>(
            pkv, k_norm, k8hp, k8lp, skp, KV_LEN, NKVH, KV_N, NKVH * HD);
    }
    // V transpose + bf16 split
    vtrans_split<<<dim3(KV_PAD / 32, HD / 32, NKVH), dim3(32, 8)>>>(pkv);

    // attention
    cudaFuncSetAttribute(attn_mma, cudaFuncAttributeMaxDynamicSharedMemorySize,
                         ATTN_SMEM);
    attn_mma<<<dim3(Q_LEN / 128, NH), 256, ATTN_SMEM>>>(mask);

    // O projection
    quant_rows<<<Q_LEN, 256>>>(pattn, attn8h, attn8l, s_attn);
    gemm_imma<<<dim3(HIDDEN / 128, Q_LEN / 128), 256, GQ_SMEM>>>(
        attn8h, attn8l, wo8h, wo8l, s_attn, sbo, out, Q_LEN, HIDDEN);
}

// round 9
// speedup vs baseline: 2.1278x; 2.1278x over previous
#include <cuda_runtime.h>
#include <cuda_bf16.h>
#include <stdint.h>
#include <math.h>

#define Q_LEN   1024
#define KV_LEN  6404
#define KV_PAD  6464
#define HIDDEN  4096
#define NH      32
#define NKVH    8
#define HD      128
#define QKV_LDB 6144
#define KV_N    2048
#define ATTN_SCALE 0.08838834764831845f

// ---------------- scratch ----------------
__device__ float g_q[Q_LEN * HIDDEN];
__device__ float g_kv[KV_LEN * KV_N];

__device__ __nv_bfloat16 g_hid_hi[Q_LEN * HIDDEN];
__device__ __nv_bfloat16 g_hid_lo[Q_LEN * HIDDEN];
__device__ __nv_bfloat16 g_cross_hi[KV_LEN * HIDDEN];
__device__ __nv_bfloat16 g_cross_lo[KV_LEN * HIDDEN];
__device__ __nv_bfloat16 g_wqkvT_hi[QKV_LDB * HIDDEN];   // [col][k]
__device__ __nv_bfloat16 g_wqkvT_lo[QKV_LDB * HIDDEN];
__device__ __nv_bfloat16 g_woT_hi[HIDDEN * HIDDEN];
__device__ __nv_bfloat16 g_woT_lo[HIDDEN * HIDDEN];
__device__ __nv_bfloat16 g_qhi[Q_LEN * HIDDEN];
__device__ __nv_bfloat16 g_qlo[Q_LEN * HIDDEN];
__device__ __nv_bfloat16 g_khi[KV_LEN * (NKVH * HD)];
__device__ __nv_bfloat16 g_klo[KV_LEN * (NKVH * HD)];
__device__ __nv_bfloat16 g_vthi[NKVH * HD * KV_PAD];
__device__ __nv_bfloat16 g_vtlo[NKVH * HD * KV_PAD];
__device__ __nv_bfloat16 g_attnhi[Q_LEN * HIDDEN];
__device__ __nv_bfloat16 g_attnlo[Q_LEN * HIDDEN];

__device__ __forceinline__ void split2(float x, float y, unsigned& hi, unsigned& lo)
{
    __nv_bfloat16 hx = __float2bfloat16(x), hy = __float2bfloat16(y);
    float lx = x - __bfloat162float(hx), ly = y - __bfloat162float(hy);
    __nv_bfloat16 lxb = __float2bfloat16(lx), lyb = __float2bfloat16(ly);
    hi = (unsigned)__bfloat16_as_ushort(hx) | ((unsigned)__bfloat16_as_ushort(hy) << 16);
    lo = (unsigned)__bfloat16_as_ushort(lxb) | ((unsigned)__bfloat16_as_ushort(lyb) << 16);
}

__device__ __forceinline__ uint32_t smem_u32(const void* p)
{
    uint32_t a;
    asm("{ .reg .u64 t; cvta.to.shared.u64 t, %1; cvt.u32.u64 %0, t; }"
        : "=r"(a) : "l"(p));
    return a;
}
#define CP16(dst, src, n) \
    asm volatile("cp.async.cg.shared.global [%0], [%1], 16, %2;" \
                 :: "r"(dst), "l"(src), "r"(n))
#define CP_COMMIT() asm volatile("cp.async.commit_group;" ::: "memory")
#define CP_WAIT0()  asm volatile("cp.async.wait_group 0;" ::: "memory")

#define MMA_BF16(d, a, b)                                                      \
    asm volatile(                                                              \
        "mma.sync.aligned.m16n8k16.row.col.f32.bf16.bf16.f32 "                 \
        "{%0,%1,%2,%3},{%4,%5,%6,%7},{%8,%9},{%0,%1,%2,%3};"                   \
        : "+f"((d)[0]), "+f"((d)[1]), "+f"((d)[2]), "+f"((d)[3])               \
        : "r"((a)[0]), "r"((a)[1]), "r"((a)[2]), "r"((a)[3]),                  \
          "r"((b)[0]), "r"((b)[1]))

// ---------------- pipelined bf16x3 GEMM: C[M,N] = A @ Bt^T, K=4096 -----------
// block 128x128, BK=32 halves (64B/row), 256 threads (8 warps, 2m x 4n),
// cp.async 2-stage ring, one __syncthreads per chunk.
#define GB_ST    80                    // bytes per smem row (64 data + 16 pad)
#define GB_BUF   (128 * GB_ST)         // one tile buffer
#define GB_STAGE (4 * GB_BUF)          // Ah, Al, Bh, Bl
#define GB_SMEM  (2 * GB_STAGE)

__global__ void __launch_bounds__(256, 1) gemm_bf16x3(
    const __nv_bfloat16* __restrict__ Ahi, const __nv_bfloat16* __restrict__ Alo,
    const __nv_bfloat16* __restrict__ Bthi, const __nv_bfloat16* __restrict__ Btlo,
    float* __restrict__ C, int M, int ldc)
{
    extern __shared__ char smg[];
    const uint32_t sb = smem_u32(smg);
    const int tid  = threadIdx.x;
    const int warp = tid >> 5, lane = tid & 31;
    const int g = lane >> 2, tig = lane & 3;
    const int wm = warp & 1, wn = warp >> 1;
    const int row0 = blockIdx.y * 128, col0 = blockIdx.x * 128;
    const int rowbase = wm * 64, colbase = wn * 32;
    const int K = HIDDEN;
    const int nck = K / 32;

    float acc[4][4][4];
#pragma unroll
    for (int i = 0; i < 4; i++)
#pragma unroll
        for (int j = 0; j < 4; j++)
#pragma unroll
            for (int t = 0; t < 4; t++) acc[i][j][t] = 0.f;

    auto load_chunk = [&](int ck, int st) {
        const uint32_t stb = sb + st * GB_STAGE;
        const int k0 = ck * 32;                 // in halves
#pragma unroll
        for (int i = 0; i < 2; i++) {
            int idx = tid + i * 256;
            int r = idx >> 2, c = idx & 3;      // 128 rows x 4 x 16B
            uint32_t soff = (uint32_t)(r * GB_ST + c * 16);
            int gr = row0 + r;
            int ok = (gr < M) ? 16 : 0;
            int grc = (gr < M) ? gr : 0;
            size_t aoff = (size_t)grc * K + k0 + c * 8;
            CP16(stb + 0 * GB_BUF + soff, Ahi + aoff, ok);
            CP16(stb + 1 * GB_BUF + soff, Alo + aoff, ok);
            size_t boff = (size_t)(col0 + r) * K + k0 + c * 8;
            CP16(stb + 2 * GB_BUF + soff, Bthi + boff, 16);
            CP16(stb + 3 * GB_BUF + soff, Btlo + boff, 16);
        }
    };

    load_chunk(0, 0);
    CP_COMMIT();

    for (int ck = 0; ck < nck; ck++) {
        const int st = ck & 1;
        CP_WAIT0();
        __syncthreads();
        if (ck + 1 < nck) {
            load_chunk(ck + 1, st ^ 1);
            CP_COMMIT();
        }
        const char* smAh = smg + (size_t)st * GB_STAGE;
        const char* smAl = smAh + GB_BUF;
        const char* smBh = smAh + 2 * GB_BUF;
        const char* smBl = smAh + 3 * GB_BUF;

#pragma unroll
        for (int ks = 0; ks < 2; ks++) {        // two k16 steps
            const int kb = ks * 32 + tig * 4;   // byte offset within row
            unsigned ah[4][4], al[4][4], bh[4][2], bl[4][2];
#pragma unroll
            for (int am = 0; am < 4; am++) {
                int base = (rowbase + am * 16 + g) * GB_ST + kb;
                ah[am][0] = *(const unsigned*)(smAh + base);
                ah[am][1] = *(const unsigned*)(smAh + base + 8 * GB_ST);
                ah[am][2] = *(const unsigned*)(smAh + base + 16);
                ah[am][3] = *(const unsigned*)(smAh + base + 8 * GB_ST + 16);
                al[am][0] = *(const unsigned*)(smAl + base);
                al[am][1] = *(const unsigned*)(smAl + base + 8 * GB_ST);
                al[am][2] = *(const unsigned*)(smAl + base + 16);
                al[am][3] = *(const unsigned*)(smAl + base + 8 * GB_ST + 16);
            }
#pragma unroll
            for (int an = 0; an < 4; an++) {
                int base = (colbase + an * 8 + g) * GB_ST + kb;
                bh[an][0] = *(const unsigned*)(smBh + base);
                bh[an][1] = *(const unsigned*)(smBh + base + 16);
                bl[an][0] = *(const unsigned*)(smBl + base);
                bl[an][1] = *(const unsigned*)(smBl + base + 16);
            }
#pragma unroll
            for (int am = 0; am < 4; am++)
#pragma unroll
                for (int an = 0; an < 4; an++) MMA_BF16(acc[am][an], ah[am], bh[an]);
#pragma unroll
            for (int am = 0; am < 4; am++)
#pragma unroll
                for (int an = 0; an < 4; an++) MMA_BF16(acc[am][an], al[am], bh[an]);
#pragma unroll
            for (int am = 0; am < 4; am++)
#pragma unroll
                for (int an = 0; an < 4; an++) MMA_BF16(acc[am][an], ah[am], bl[an]);
        }
    }

    // ---- epilogue ----
#pragma unroll
    for (int am = 0; am < 4; am++) {
#pragma unroll
        for (int an = 0; an < 4; an++) {
            int r = row0 + rowbase + am * 16 + g;
            int c = col0 + colbase + an * 8 + tig * 2;
            if (r < M)
                *(float2*)(C + (size_t)r * ldc + c) =
                    make_float2(acc[am][an][0], acc[am][an][1]);
            if (r + 8 < M)
                *(float2*)(C + (size_t)(r + 8) * ldc + c) =
                    make_float2(acc[am][an][2], acc[am][an][3]);
        }
    }
}

// ---------------- fp32 -> bf16 hi/lo split ----------------
__global__ void split_kernel(const float* __restrict__ x,
                             __nv_bfloat16* __restrict__ hi,
                             __nv_bfloat16* __restrict__ lo, int n4)
{
    int i = blockIdx.x * blockDim.x + threadIdx.x;
    if (i >= n4) return;
    float4 v = ((const float4*)x)[i];
    uint2 uh, ul;
    split2(v.x, v.y, uh.x, ul.x);
    split2(v.z, v.w, uh.y, ul.y);
    ((uint2*)hi)[i] = uh;
    ((uint2*)lo)[i] = ul;
}

// ---------------- fp32 [R][C] -> bf16 hi/lo [C][R] ----------------
__global__ void wtrans_split(const float* __restrict__ w,
                             __nv_bfloat16* __restrict__ hi,
                             __nv_bfloat16* __restrict__ lo, int R, int C)
{
    __shared__ float t[32][33];
    int tx = threadIdx.x, ty = threadIdx.y;
    int r0 = blockIdx.y * 32, c0 = blockIdx.x * 32;
#pragma unroll
    for (int i = 0; i < 4; i++)
        t[ty + 8 * i][tx] = w[(size_t)(r0 + ty + 8 * i) * C + c0 + tx];
    __syncthreads();
#pragma unroll
    for (int i = 0; i < 4; i++) {
        float v = t[tx][ty + 8 * i];
        __nv_bfloat16 hb = __float2bfloat16(v);
        __nv_bfloat16 lb = __float2bfloat16(v - __bfloat162float(hb));
        size_t off = (size_t)(c0 + ty + 8 * i) * R + r0 + tx;
        hi[off] = hb; lo[off] = lb;
    }
}

// ---------------- V transpose+split ----------------
__global__ void vtrans_split(const float* __restrict__ kv)
{
    __shared__ float t[32][33];
    int tx = threadIdx.x, ty = threadIdx.y;
    int kv0 = blockIdx.x * 32, d0 = blockIdx.y * 32, kvh = blockIdx.z;
#pragma unroll
    for (int i = 0; i < 4; i++) {
        int r = kv0 + ty + 8 * i;
        t[ty + 8 * i][tx] = (r < KV_LEN)
            ? kv[(size_t)r * KV_N + NKVH * HD + kvh * HD + d0 + tx] : 0.f;
    }
    __syncthreads();
#pragma unroll
    for (int i = 0; i < 4; i++) {
        float v = t[tx][ty + 8 * i];
        __nv_bfloat16 hb = __float2bfloat16(v);
        __nv_bfloat16 lb = __float2bfloat16(v - __bfloat162float(hb));
        size_t off = (size_t)(kvh * HD + d0 + ty + 8 * i) * KV_PAD + kv0 + tx;
        g_vthi[off] = hb; g_vtlo[off] = lb;
    }
}

// ---------------- RMS norm fp32 -> bf16 hi/lo ----------------
__global__ void rmsnorm_split(const float* __restrict__ x, const float* __restrict__ w,
                              __nv_bfloat16* __restrict__ hi, __nv_bfloat16* __restrict__ lo,
                              int nrows, int nheads, int ld_in, int ld_out)
{
    int gw = (int)((blockIdx.x * blockDim.x + threadIdx.x) >> 5);
    int lane = threadIdx.x & 31;
    if (gw >= nrows * nheads) return;
    int row = gw / nheads, h = gw - row * nheads;
    const float* p = x + (size_t)row * ld_in + h * HD;
    float4 v = *(const float4*)(p + lane * 4);
    float ss = v.x * v.x + v.y * v.y + v.z * v.z + v.w * v.w;
#pragma unroll
    for (int o = 16; o > 0; o >>= 1) ss += __shfl_xor_sync(0xffffffffu, ss, o);
    float s = rsqrtf(ss * (1.f / HD) + 1e-5f);
    float4 wv = *(const float4*)(w + lane * 4);
    v.x *= s * wv.x; v.y *= s * wv.y; v.z *= s * wv.z; v.w *= s * wv.w;
    uint2 uh, ul;
    split2(v.x, v.y, uh.x, ul.x);
    split2(v.z, v.w, uh.y, ul.y);
    size_t off = (size_t)row * ld_out + h * HD + lane * 4;
    *(uint2*)(hi + off) = uh;
    *(uint2*)(lo + off) = ul;
}

// ---------------- mma.sync flash attention (R3, unchanged) ----------------
#define QST 136
#define KST 136
#define VST 72
#define ATTN_SMEM ((2*128*QST + 2*64*KST + 2*128*VST) * 2)

__global__ void __launch_bounds__(256, 1) attn_mma(const float* __restrict__ mask)
{
    extern __shared__ __nv_bfloat16 sm[];
    __nv_bfloat16* Qh = sm;
    __nv_bfloat16* Ql = Qh + 128 * QST;
    __nv_bfloat16* Kh = Ql + 128 * QST;
    __nv_bfloat16* Kl = Kh + 64 * KST;
    __nv_bfloat16* Vh = Kl + 64 * KST;
    __nv_bfloat16* Vl = Vh + 128 * VST;

    const int tid = threadIdx.x, warp = tid >> 5, lane = tid & 31;
    const int g = lane >> 2, tig = lane & 3;
    const int h = blockIdx.y, kvh = h >> 2;
    const int q0 = blockIdx.x * 128;
    const int wr = warp * 16;
    const int row0 = q0 + wr + g;

#pragma unroll
    for (int it = 0; it < 8; it++) {
        int idx = tid + it * 256;
        int r = idx >> 4, c = (idx & 15) * 8;
        size_t off = (size_t)(q0 + r) * HIDDEN + h * HD + c;
        *(uint4*)&Qh[r * QST + c] = *(const uint4*)(g_qhi + off);
        *(uint4*)&Ql[r * QST + c] = *(const uint4*)(g_qlo + off);
    }

    float o[16][4];
#pragma unroll
    for (int n = 0; n < 16; n++)
#pragma unroll
        for (int t = 0; t < 4; t++) o[n][t] = 0.f;
    float m0 = -1e30f, m1 = -1e30f, l0 = 0.f, l1 = 0.f;

    for (int kv0 = 0; kv0 < KV_LEN; kv0 += 64) {
        __syncthreads();
#pragma unroll
        for (int it = 0; it < 4; it++) {
            int idx = tid + it * 256;
            int r = idx >> 4, c = (idx & 15) * 8;
            uint4 vh = make_uint4(0, 0, 0, 0), vl = vh;
            if (kv0 + r < KV_LEN) {
                size_t off = (size_t)(kv0 + r) * (NKVH * HD) + kvh * HD + c;
                vh = *(const uint4*)(g_khi + off);
                vl = *(const uint4*)(g_klo + off);
            }
            *(uint4*)&Kh[r * KST + c] = vh;
            *(uint4*)&Kl[r * KST + c] = vl;
        }
#pragma unroll
        for (int it = 0; it < 4; it++) {
            int idx = tid + it * 256;
            int d = idx >> 3, c = (idx & 7) * 8;
            size_t off = ((size_t)kvh * HD + d) * KV_PAD + kv0 + c;
            *(uint4*)&Vh[d * VST + c] = *(const uint4*)(g_vthi + off);
            *(uint4*)&Vl[d * VST + c] = *(const uint4*)(g_vtlo + off);
        }
        __syncthreads();

        float s[8][4];
#pragma unroll
        for (int j = 0; j < 8; j++)
#pragma unroll
            for (int c = 0; c < 4; c++) s[j][c] = 0.f;

#pragma unroll
        for (int kt = 0; kt < 8; kt++) {
            int ab = (wr + g) * QST + kt * 16 + tig * 2;
            unsigned ah[4], al[4];
            ah[0] = *(const unsigned*)&Qh[ab];
            ah[1] = *(const unsigned*)&Qh[ab + 8 * QST];
            ah[2] = *(const unsigned*)&Qh[ab + 8];
            ah[3] = *(const unsigned*)&Qh[ab + 8 * QST + 8];
            al[0] = *(const unsigned*)&Ql[ab];
            al[1] = *(const unsigned*)&Ql[ab + 8 * QST];
            al[2] = *(const unsigned*)&Ql[ab + 8];
            al[3] = *(const unsigned*)&Ql[ab + 8 * QST + 8];
#pragma unroll
            for (int j = 0; j < 8; j++) {
                int bb = (8 * j + g) * KST + kt * 16 + tig * 2;
                unsigned bh[2], bl[2];
                bh[0] = *(const unsigned*)&Kh[bb];
                bh[1] = *(const unsigned*)&Kh[bb + 8];
                bl[0] = *(const unsigned*)&Kl[bb];
                bl[1] = *(const unsigned*)&Kl[bb + 8];
                MMA_BF16(s[j], ah, bh);
                MMA_BF16(s[j], al, bh);
                MMA_BF16(s[j], ah, bl);
            }
        }

        bool partial = (kv0 + 64 > KV_LEN);
        float rmax0 = -1e30f, rmax1 = -1e30f;
        if (!partial) {
#pragma unroll
            for (int j = 0; j < 8; j++) {
                int col = kv0 + 8 * j + tig * 2;
                const float* mp = mask + (size_t)row0 * KV_LEN + col;
                float2 mk0 = *(const float2*)mp;
                float2 mk1 = *(const float2*)(mp + (size_t)8 * KV_LEN);
                s[j][0] = fmaf(s[j][0], ATTN_SCALE, mk0.x);
                s[j][1] = fmaf(s[j][1], ATTN_SCALE, mk0.y);
                s[j][2] = fmaf(s[j][2], ATTN_SCALE, mk1.x);
                s[j][3] = fmaf(s[j][3], ATTN_SCALE, mk1.y);
                rmax0 = fmaxf(rmax0, fmaxf(s[j][0], s[j][1]));
                rmax1 = fmaxf(rmax1, fmaxf(s[j][2], s[j][3]));
            }
        } else {
#pragma unroll
            for (int j = 0; j < 8; j++) {
#pragma unroll
                for (int c = 0; c < 2; c++) {
                    int col = kv0 + 8 * j + tig * 2 + c;
                    if (col < KV_LEN) {
                        s[j][c]     = fmaf(s[j][c], ATTN_SCALE,
                                           mask[(size_t)row0 * KV_LEN + col]);
                        s[j][2 + c] = fmaf(s[j][2 + c], ATTN_SCALE,
                                           mask[(size_t)(row0 + 8) * KV_LEN + col]);
                    } else {
                        s[j][c] = -1e30f;
                        s[j][2 + c] = -1e30f;
                    }
                }
                rmax0 = fmaxf(rmax0, fmaxf(s[j][0], s[j][1]));
                rmax1 = fmaxf(rmax1, fmaxf(s[j][2], s[j][3]));
            }
        }
        rmax0 = fmaxf(rmax0, __shfl_xor_sync(0xffffffffu, rmax0, 1));
        rmax0 = fmaxf(rmax0, __shfl_xor_sync(0xffffffffu, rmax0, 2));
        rmax1 = fmaxf(rmax1, __shfl_xor_sync(0xffffffffu, rmax1, 1));
        rmax1 = fmaxf(rmax1, __shfl_xor_sync(0xffffffffu, rmax1, 2));

        float mn0 = fmaxf(m0, rmax0), mn1 = fmaxf(m1, rmax1);
        float f0 = __expf(m0 - mn0), f1 = __expf(m1 - mn1);
        m0 = mn0; m1 = mn1;

        float sum0 = 0.f, sum1 = 0.f;
#pragma unroll
        for (int j = 0; j < 8; j++) {
            s[j][0] = __expf(s[j][0] - mn0);
            s[j][1] = __expf(s[j][1] - mn0);
            s[j][2] = __expf(s[j][2] - mn1);
            s[j][3] = __expf(s[j][3] - mn1);
            sum0 += s[j][0] + s[j][1];
            sum1 += s[j][2] + s[j][3];
        }
        sum0 += __shfl_xor_sync(0xffffffffu, sum0, 1);
        sum0 += __shfl_xor_sync(0xffffffffu, sum0, 2);
        sum1 += __shfl_xor_sync(0xffffffffu, sum1, 1);
        sum1 += __shfl_xor_sync(0xffffffffu, sum1, 2);
        l0 = l0 * f0 + sum0;
        l1 = l1 * f1 + sum1;

#pragma unroll
        for (int n = 0; n < 16; n++) {
            o[n][0] *= f0; o[n][1] *= f0; o[n][2] *= f1; o[n][3] *= f1;
        }

#pragma unroll
        for (int t = 0; t < 4; t++) {
            unsigned ph[4], pl[4];
            split2(s[2 * t][0],     s[2 * t][1],     ph[0], pl[0]);
            split2(s[2 * t][2],     s[2 * t][3],     ph[1], pl[1]);
            split2(s[2 * t + 1][0], s[2 * t + 1][1], ph[2], pl[2]);
            split2(s[2 * t + 1][2], s[2 * t + 1][3], ph[3], pl[3]);
#pragma unroll
            for (int n = 0; n < 16; n++) {
                int vb = (8 * n + g) * VST + t * 16 + tig * 2;
                unsigned bh[2], bl[2];
                bh[0] = *(const unsigned*)&Vh[vb];
                bh[1] = *(const unsigned*)&Vh[vb + 8];
                bl[0] = *(const unsigned*)&Vl[vb];
                bl[1] = *(const unsigned*)&Vl[vb + 8];
                MMA_BF16(o[n], ph, bh);
                MMA_BF16(o[n], pl, bh);
                MMA_BF16(o[n], ph, bl);
            }
        }
    }

    float il0 = 1.f / l0, il1 = 1.f / l1;
#pragma unroll
    for (int n = 0; n < 16; n++) {
        unsigned h01, lo01, h23, lo23;
        split2(o[n][0] * il0, o[n][1] * il0, h01, lo01);
        split2(o[n][2] * il1, o[n][3] * il1, h23, lo23);
        size_t base = (size_t)row0 * HIDDEN + h * HD + 8 * n + tig * 2;
        *(unsigned*)(g_attnhi + base) = h01;
        *(unsigned*)(g_attnlo + base) = lo01;
        *(unsigned*)(g_attnhi + base + (size_t)8 * HIDDEN) = h23;
        *(unsigned*)(g_attnlo + base + (size_t)8 * HIDDEN) = lo23;
    }
}

// ---------------------------------------------------------------------------
extern "C" void kernel_launch(void* const* d_in, const int* in_sizes, int n_in,
                              void* d_out, int out_size)
{
    const float* hidden = (const float*)d_in[0];
    const float* cross  = (const float*)d_in[1];
    const float* mask   = (const float*)d_in[2];
    const float* w_qkv  = (const float*)d_in[3];
    const float* w_o    = (const float*)d_in[4];
    const float* q_norm = (const float*)d_in[5];
    const float* k_norm = (const float*)d_in[6];
    float* out = (float*)d_out;
    (void)in_sizes; (void)n_in; (void)out_size;

    float *pq, *pkv;
    cudaGetSymbolAddress((void**)&pq,  g_q);
    cudaGetSymbolAddress((void**)&pkv, g_kv);
    __nv_bfloat16 *hid_hi, *hid_lo, *cross_hi, *cross_lo;
    __nv_bfloat16 *wqkvT_hi, *wqkvT_lo, *woT_hi, *woT_lo;
    __nv_bfloat16 *qhi, *qlo, *khi, *klo, *attnhi, *attnlo;
    cudaGetSymbolAddress((void**)&hid_hi,   g_hid_hi);
    cudaGetSymbolAddress((void**)&hid_lo,   g_hid_lo);
    cudaGetSymbolAddress((void**)&cross_hi, g_cross_hi);
    cudaGetSymbolAddress((void**)&cross_lo, g_cross_lo);
    cudaGetSymbolAddress((void**)&wqkvT_hi, g_wqkvT_hi);
    cudaGetSymbolAddress((void**)&wqkvT_lo, g_wqkvT_lo);
    cudaGetSymbolAddress((void**)&woT_hi,   g_woT_hi);
    cudaGetSymbolAddress((void**)&woT_lo,   g_woT_lo);
    cudaGetSymbolAddress((void**)&qhi,      g_qhi);
    cudaGetSymbolAddress((void**)&qlo,      g_qlo);
    cudaGetSymbolAddress((void**)&khi,      g_khi);
    cudaGetSymbolAddress((void**)&klo,      g_klo);
    cudaGetSymbolAddress((void**)&attnhi,   g_attnhi);
    cudaGetSymbolAddress((void**)&attnlo,   g_attnlo);

    // activations split
    {
        int n4 = Q_LEN * HIDDEN / 4;
        split_kernel<<<(n4 + 255) / 256, 256>>>(hidden, hid_hi, hid_lo, n4);
        n4 = KV_LEN * HIDDEN / 4;
        split_kernel<<<(n4 + 255) / 256, 256>>>(cross, cross_hi, cross_lo, n4);
    }
    // weight transpose + split
    wtrans_split<<<dim3(QKV_LDB / 32, HIDDEN / 32), dim3(32, 8)>>>(
        w_qkv, wqkvT_hi, wqkvT_lo, HIDDEN, QKV_LDB);
    wtrans_split<<<dim3(HIDDEN / 32, HIDDEN / 32), dim3(32, 8)>>>(
        w_o, woT_hi, woT_lo, HIDDEN, HIDDEN);

    cudaFuncSetAttribute(gemm_bf16x3, cudaFuncAttributeMaxDynamicSharedMemorySize,
                         GB_SMEM);

    // Q projection: M=1024, N=4096
    gemm_bf16x3<<<dim3(HIDDEN / 128, Q_LEN / 128), 256, GB_SMEM>>>(
        hid_hi, hid_lo, wqkvT_hi, wqkvT_lo, pq, Q_LEN, HIDDEN);
    // KV projection: M=6404, N=2048 (wqkvT rows 4096..6143)
    gemm_bf16x3<<<dim3(KV_N / 128, (KV_LEN + 127) / 128), 256, GB_SMEM>>>(
        cross_hi, cross_lo,
        wqkvT_hi + (size_t)(NH * HD) * HIDDEN, wqkvT_lo + (size_t)(NH * HD) * HIDDEN,
        pkv, KV_LEN, KV_N);

    // RMS norms -> bf16 hi/lo
    {
        int nwarps = Q_LEN * NH;
        rmsnorm_split<<<(nwarps * 32 + 255) / 256, 256>>>(
            pq, q_norm, qhi, qlo, Q_LEN, NH, HIDDEN, HIDDEN);
        nwarps = KV_LEN * NKVH;
        rmsnorm_split<<<(nwarps * 32 + 255) / 256, 256>>>(
            pkv, k_norm, khi, klo, KV_LEN, NKVH, KV_N, NKVH * HD);
    }
    // V transpose + split
    vtrans_split<<<dim3(KV_PAD / 32, HD / 32, NKVH), dim3(32, 8)>>>(pkv);

    // attention
    cudaFuncSetAttribute(attn_mma, cudaFuncAttributeMaxDynamicSharedMemorySize,
                         ATTN_SMEM);
    attn_mma<<<dim3(Q_LEN / 128, NH), 256, ATTN_SMEM>>>(mask);

    // O projection: M=1024, N=4096
    gemm_bf16x3<<<dim3(HIDDEN / 128, Q_LEN / 128), 256, GB_SMEM>>>(
        attnhi, attnlo, woT_hi, woT_lo, out, Q_LEN, HIDDEN);
}

// round 10
// speedup vs baseline: 2.4864x; 1.1685x over previous
#include <cuda_runtime.h>
#include <cuda_bf16.h>
#include <stdint.h>
#include <math.h>

#define Q_LEN   1024
#define KV_LEN  6404
#define KV_PAD  6464
#define HIDDEN  4096
#define NH      32
#define NKVH    8
#define HD      128
#define QKV_LDB 6144
#define KV_N    2048
#define ATTN_SCALE 0.08838834764831845f

// ---------------- scratch ----------------
__device__ float g_q[Q_LEN * HIDDEN];
__device__ float g_kv[KV_LEN * KV_N];

__device__ __nv_bfloat16 g_hid_hi[Q_LEN * HIDDEN];
__device__ __nv_bfloat16 g_hid_lo[Q_LEN * HIDDEN];
__device__ __nv_bfloat16 g_cross_hi[KV_LEN * HIDDEN];
__device__ __nv_bfloat16 g_cross_lo[KV_LEN * HIDDEN];
__device__ __nv_bfloat16 g_wqkvT_hi[QKV_LDB * HIDDEN];   // [col][k]
__device__ __nv_bfloat16 g_wqkvT_lo[QKV_LDB * HIDDEN];
__device__ __nv_bfloat16 g_woT_hi[HIDDEN * HIDDEN];
__device__ __nv_bfloat16 g_woT_lo[HIDDEN * HIDDEN];
__device__ __nv_bfloat16 g_qhi[Q_LEN * HIDDEN];
__device__ __nv_bfloat16 g_qlo[Q_LEN * HIDDEN];
__device__ __nv_bfloat16 g_khi[KV_LEN * (NKVH * HD)];
__device__ __nv_bfloat16 g_klo[KV_LEN * (NKVH * HD)];
__device__ __nv_bfloat16 g_vthi[NKVH * HD * KV_PAD];
__device__ __nv_bfloat16 g_vtlo[NKVH * HD * KV_PAD];
__device__ __nv_bfloat16 g_attnhi[Q_LEN * HIDDEN];
__device__ __nv_bfloat16 g_attnlo[Q_LEN * HIDDEN];

__device__ __forceinline__ void split2(float x, float y, unsigned& hi, unsigned& lo)
{
    __nv_bfloat16 hx = __float2bfloat16(x), hy = __float2bfloat16(y);
    float lx = x - __bfloat162float(hx), ly = y - __bfloat162float(hy);
    __nv_bfloat16 lxb = __float2bfloat16(lx), lyb = __float2bfloat16(ly);
    hi = (unsigned)__bfloat16_as_ushort(hx) | ((unsigned)__bfloat16_as_ushort(hy) << 16);
    lo = (unsigned)__bfloat16_as_ushort(lxb) | ((unsigned)__bfloat16_as_ushort(lyb) << 16);
}

__device__ __forceinline__ uint32_t smem_u32(const void* p)
{
    uint32_t a;
    asm("{ .reg .u64 t; cvta.to.shared.u64 t, %1; cvt.u32.u64 %0, t; }"
        : "=r"(a) : "l"(p));
    return a;
}
#define CP16(dst, src, n) \
    asm volatile("cp.async.cg.shared.global [%0], [%1], 16, %2;" \
                 :: "r"(dst), "l"(src), "r"(n))
#define CP_COMMIT() asm volatile("cp.async.commit_group;" ::: "memory")
#define CP_WAIT1()  asm volatile("cp.async.wait_group 1;" ::: "memory")

#define MMA_BF16(d, a, b)                                                      \
    asm volatile(                                                              \
        "mma.sync.aligned.m16n8k16.row.col.f32.bf16.bf16.f32 "                 \
        "{%0,%1,%2,%3},{%4,%5,%6,%7},{%8,%9},{%0,%1,%2,%3};"                   \
        : "+f"((d)[0]), "+f"((d)[1]), "+f"((d)[2]), "+f"((d)[3])               \
        : "r"((a)[0]), "r"((a)[1]), "r"((a)[2]), "r"((a)[3]),                  \
          "r"((b)[0]), "r"((b)[1]))

// ---------------- pipelined bf16x3 GEMM: C[M,N] = A @ Bt^T, K=4096 -----------
// block 128x128, BK=64 halves (128B rows, SW128 xor swizzle), 256 threads,
// 3-stage cp.async ring, conflict-free stores and fragment loads.
#define GB_BUF   (128 * 128)           // one tile buffer (bytes)
#define GB_STAGE (4 * GB_BUF)          // Ah, Al, Bh, Bl = 64KB
#define GB_NST   3
#define GB_SMEM  (GB_NST * GB_STAGE)   // 192KB

__global__ void __launch_bounds__(256, 1) gemm_bf16x3(
    const __nv_bfloat16* __restrict__ Ahi, const __nv_bfloat16* __restrict__ Alo,
    const __nv_bfloat16* __restrict__ Bthi, const __nv_bfloat16* __restrict__ Btlo,
    float* __restrict__ C, int M, int ldc)
{
    extern __shared__ char smg[];
    const uint32_t sb = smem_u32(smg);
    const int tid  = threadIdx.x;
    const int warp = tid >> 5, lane = tid & 31;
    const int g = lane >> 2, tig = lane & 3;
    const int wm = warp & 1, wn = warp >> 1;
    const int row0 = blockIdx.y * 128, col0 = blockIdx.x * 128;
    const int rowbase = wm * 64, colbase = wn * 32;
    const int K = HIDDEN;
    const int nck = K / 64;

    float acc[4][4][4];
#pragma unroll
    for (int i = 0; i < 4; i++)
#pragma unroll
        for (int j = 0; j < 4; j++)
#pragma unroll
            for (int t = 0; t < 4; t++) acc[i][j][t] = 0.f;

    auto load_chunk = [&](int ck, int st) {
        const uint32_t stb = sb + st * GB_STAGE;
        const int k0 = ck * 64;                 // halves
#pragma unroll
        for (int i = 0; i < 4; i++) {
            int idx = tid + i * 256;            // 0..1023
            int r = idx >> 3, c = idx & 7;      // 128 rows x 8 chunks of 16B
            uint32_t soff = (uint32_t)(r * 128 + ((c ^ (r & 7)) * 16));
            int gr = row0 + r;
            int ok = (gr < M) ? 16 : 0;
            int grc = (gr < M) ? gr : 0;
            size_t aoff = (size_t)grc * K + k0 + c * 8;
            CP16(stb + 0 * GB_BUF + soff, Ahi + aoff, ok);
            CP16(stb + 1 * GB_BUF + soff, Alo + aoff, ok);
            size_t boff = (size_t)(col0 + r) * K + k0 + c * 8;
            CP16(stb + 2 * GB_BUF + soff, Bthi + boff, 16);
            CP16(stb + 3 * GB_BUF + soff, Btlo + boff, 16);
        }
    };

    load_chunk(0, 0); CP_COMMIT();
    load_chunk(1, 1); CP_COMMIT();

    for (int ck = 0; ck < nck; ck++) {
        const int st = ck % GB_NST;
        CP_WAIT1();                 // oldest (chunk ck) complete, ck+1 may fly
        __syncthreads();
        if (ck + 2 < nck) load_chunk(ck + 2, (ck + 2) % GB_NST);
        CP_COMMIT();                // unconditional: keeps 2 groups pending

        const char* smAh = smg + (size_t)st * GB_STAGE;
        const char* smAl = smAh + GB_BUF;
        const char* smBh = smAh + 2 * GB_BUF;
        const char* smBl = smAh + 3 * GB_BUF;

#pragma unroll
        for (int ks = 0; ks < 4; ks++) {        // four k16 steps
            const int c0 = ks * 2;
            const int s0 = ((c0 ^ g) * 16) + tig * 4;
            const int s1 = (((c0 + 1) ^ g) * 16) + tig * 4;
            unsigned ah[4][4], al[4][4], bh[4][2], bl[4][2];
#pragma unroll
            for (int am = 0; am < 4; am++) {
                int base = (rowbase + am * 16 + g) * 128;
                ah[am][0] = *(const unsigned*)(smAh + base + s0);
                ah[am][1] = *(const unsigned*)(smAh + base + 8 * 128 + s0);
                ah[am][2] = *(const unsigned*)(smAh + base + s1);
                ah[am][3] = *(const unsigned*)(smAh + base + 8 * 128 + s1);
                al[am][0] = *(const unsigned*)(smAl + base + s0);
                al[am][1] = *(const unsigned*)(smAl + base + 8 * 128 + s0);
                al[am][2] = *(const unsigned*)(smAl + base + s1);
                al[am][3] = *(const unsigned*)(smAl + base + 8 * 128 + s1);
            }
#pragma unroll
            for (int an = 0; an < 4; an++) {
                int base = (colbase + an * 8 + g) * 128;
                bh[an][0] = *(const unsigned*)(smBh + base + s0);
                bh[an][1] = *(const unsigned*)(smBh + base + s1);
                bl[an][0] = *(const unsigned*)(smBl + base + s0);
                bl[an][1] = *(const unsigned*)(smBl + base + s1);
            }
#pragma unroll
            for (int am = 0; am < 4; am++)
#pragma unroll
                for (int an = 0; an < 4; an++) MMA_BF16(acc[am][an], ah[am], bh[an]);
#pragma unroll
            for (int am = 0; am < 4; am++)
#pragma unroll
                for (int an = 0; an < 4; an++) MMA_BF16(acc[am][an], al[am], bh[an]);
#pragma unroll
            for (int am = 0; am < 4; am++)
#pragma unroll
                for (int an = 0; an < 4; an++) MMA_BF16(acc[am][an], ah[am], bl[an]);
        }
        __syncthreads();
    }

    // ---- epilogue ----
#pragma unroll
    for (int am = 0; am < 4; am++) {
#pragma unroll
        for (int an = 0; an < 4; an++) {
            int r = row0 + rowbase + am * 16 + g;
            int c = col0 + colbase + an * 8 + tig * 2;
            if (r < M)
                *(float2*)(C + (size_t)r * ldc + c) =
                    make_float2(acc[am][an][0], acc[am][an][1]);
            if (r + 8 < M)
                *(float2*)(C + (size_t)(r + 8) * ldc + c) =
                    make_float2(acc[am][an][2], acc[am][an][3]);
        }
    }
}

// ---------------- fused fp32 -> bf16 hi/lo split of both activations ---------
__global__ void split_acts(const float* __restrict__ hid, const float* __restrict__ cross)
{
    const int nh = Q_LEN * HIDDEN / 4;
    const int nc = KV_LEN * HIDDEN / 4;
    int i = blockIdx.x * blockDim.x + threadIdx.x;
    if (i >= nh + nc) return;
    const float4* src;
    __nv_bfloat16 *hi, *lo;
    int j;
    if (i < nh) { src = (const float4*)hid;   hi = g_hid_hi;   lo = g_hid_lo;   j = i; }
    else        { src = (const float4*)cross; hi = g_cross_hi; lo = g_cross_lo; j = i - nh; }
    float4 v = src[j];
    uint2 uh, ul;
    split2(v.x, v.y, uh.x, ul.x);
    split2(v.z, v.w, uh.y, ul.y);
    ((uint2*)hi)[j] = uh;
    ((uint2*)lo)[j] = ul;
}

// ---------------- fp32 [R][C] -> bf16 hi/lo [C][R] ----------------
__global__ void wtrans_split(const float* __restrict__ w,
                             __nv_bfloat16* __restrict__ hi,
                             __nv_bfloat16* __restrict__ lo, int R, int C)
{
    __shared__ float t[32][33];
    int tx = threadIdx.x, ty = threadIdx.y;
    int r0 = blockIdx.y * 32, c0 = blockIdx.x * 32;
#pragma unroll
    for (int i = 0; i < 4; i++)
        t[ty + 8 * i][tx] = w[(size_t)(r0 + ty + 8 * i) * C + c0 + tx];
    __syncthreads();
#pragma unroll
    for (int i = 0; i < 4; i++) {
        float v = t[tx][ty + 8 * i];
        __nv_bfloat16 hb = __float2bfloat16(v);
        __nv_bfloat16 lb = __float2bfloat16(v - __bfloat162float(hb));
        size_t off = (size_t)(c0 + ty + 8 * i) * R + r0 + tx;
        hi[off] = hb; lo[off] = lb;
    }
}

// ---------------- V transpose+split ----------------
__global__ void vtrans_split(const float* __restrict__ kv)
{
    __shared__ float t[32][33];
    int tx = threadIdx.x, ty = threadIdx.y;
    int kv0 = blockIdx.x * 32, d0 = blockIdx.y * 32, kvh = blockIdx.z;
#pragma unroll
    for (int i = 0; i < 4; i++) {
        int r = kv0 + ty + 8 * i;
        t[ty + 8 * i][tx] = (r < KV_LEN)
            ? kv[(size_t)r * KV_N + NKVH * HD + kvh * HD + d0 + tx] : 0.f;
    }
    __syncthreads();
#pragma unroll
    for (int i = 0; i < 4; i++) {
        float v = t[tx][ty + 8 * i];
        __nv_bfloat16 hb = __float2bfloat16(v);
        __nv_bfloat16 lb = __float2bfloat16(v - __bfloat162float(hb));
        size_t off = (size_t)(kvh * HD + d0 + ty + 8 * i) * KV_PAD + kv0 + tx;
        g_vthi[off] = hb; g_vtlo[off] = lb;
    }
}

// ---------------- RMS norm fp32 -> bf16 hi/lo ----------------
__global__ void rmsnorm_split(const float* __restrict__ x, const float* __restrict__ w,
                              __nv_bfloat16* __restrict__ hi, __nv_bfloat16* __restrict__ lo,
                              int nrows, int nheads, int ld_in, int ld_out)
{
    int gw = (int)((blockIdx.x * blockDim.x + threadIdx.x) >> 5);
    int lane = threadIdx.x & 31;
    if (gw >= nrows * nheads) return;
    int row = gw / nheads, h = gw - row * nheads;
    const float* p = x + (size_t)row * ld_in + h * HD;
    float4 v = *(const float4*)(p + lane * 4);
    float ss = v.x * v.x + v.y * v.y + v.z * v.z + v.w * v.w;
#pragma unroll
    for (int o = 16; o > 0; o >>= 1) ss += __shfl_xor_sync(0xffffffffu, ss, o);
    float s = rsqrtf(ss * (1.f / HD) + 1e-5f);
    float4 wv = *(const float4*)(w + lane * 4);
    v.x *= s * wv.x; v.y *= s * wv.y; v.z *= s * wv.z; v.w *= s * wv.w;
    uint2 uh, ul;
    split2(v.x, v.y, uh.x, ul.x);
    split2(v.z, v.w, uh.y, ul.y);
    size_t off = (size_t)row * ld_out + h * HD + lane * 4;
    *(uint2*)(hi + off) = uh;
    *(uint2*)(lo + off) = ul;
}

// ---------------- mma.sync flash attention (R3, unchanged) ----------------
#define QST 136
#define KST 136
#define VST 72
#define ATTN_SMEM ((2*128*QST + 2*64*KST + 2*128*VST) * 2)

__global__ void __launch_bounds__(256, 1) attn_mma(const float* __restrict__ mask)
{
    extern __shared__ __nv_bfloat16 sm[];
    __nv_bfloat16* Qh = sm;
    __nv_bfloat16* Ql = Qh + 128 * QST;
    __nv_bfloat16* Kh = Ql + 128 * QST;
    __nv_bfloat16* Kl = Kh + 64 * KST;
    __nv_bfloat16* Vh = Kl + 64 * KST;
    __nv_bfloat16* Vl = Vh + 128 * VST;

    const int tid = threadIdx.x, warp = tid >> 5, lane = tid & 31;
    const int g = lane >> 2, tig = lane & 3;
    const int h = blockIdx.y, kvh = h >> 2;
    const int q0 = blockIdx.x * 128;
    const int wr = warp * 16;
    const int row0 = q0 + wr + g;

#pragma unroll
    for (int it = 0; it < 8; it++) {
        int idx = tid + it * 256;
        int r = idx >> 4, c = (idx & 15) * 8;
        size_t off = (size_t)(q0 + r) * HIDDEN + h * HD + c;
        *(uint4*)&Qh[r * QST + c] = *(const uint4*)(g_qhi + off);
        *(uint4*)&Ql[r * QST + c] = *(const uint4*)(g_qlo + off);
    }

    float o[16][4];
#pragma unroll
    for (int n = 0; n < 16; n++)
#pragma unroll
        for (int t = 0; t < 4; t++) o[n][t] = 0.f;
    float m0 = -1e30f, m1 = -1e30f, l0 = 0.f, l1 = 0.f;

    for (int kv0 = 0; kv0 < KV_LEN; kv0 += 64) {
        __syncthreads();
#pragma unroll
        for (int it = 0; it < 4; it++) {
            int idx = tid + it * 256;
            int r = idx >> 4, c = (idx & 15) * 8;
            uint4 vh = make_uint4(0, 0, 0, 0), vl = vh;
            if (kv0 + r < KV_LEN) {
                size_t off = (size_t)(kv0 + r) * (NKVH * HD) + kvh * HD + c;
                vh = *(const uint4*)(g_khi + off);
                vl = *(const uint4*)(g_klo + off);
            }
            *(uint4*)&Kh[r * KST + c] = vh;
            *(uint4*)&Kl[r * KST + c] = vl;
        }
#pragma unroll
        for (int it = 0; it < 4; it++) {
            int idx = tid + it * 256;
            int d = idx >> 3, c = (idx & 7) * 8;
            size_t off = ((size_t)kvh * HD + d) * KV_PAD + kv0 + c;
            *(uint4*)&Vh[d * VST + c] = *(const uint4*)(g_vthi + off);
            *(uint4*)&Vl[d * VST + c] = *(const uint4*)(g_vtlo + off);
        }
        __syncthreads();

        float s[8][4];
#pragma unroll
        for (int j = 0; j < 8; j++)
#pragma unroll
            for (int c = 0; c < 4; c++) s[j][c] = 0.f;

#pragma unroll
        for (int kt = 0; kt < 8; kt++) {
            int ab = (wr + g) * QST + kt * 16 + tig * 2;
            unsigned ah[4], al[4];
            ah[0] = *(const unsigned*)&Qh[ab];
            ah[1] = *(const unsigned*)&Qh[ab + 8 * QST];
            ah[2] = *(const unsigned*)&Qh[ab + 8];
            ah[3] = *(const unsigned*)&Qh[ab + 8 * QST + 8];
            al[0] = *(const unsigned*)&Ql[ab];
            al[1] = *(const unsigned*)&Ql[ab + 8 * QST];
            al[2] = *(const unsigned*)&Ql[ab + 8];
            al[3] = *(const unsigned*)&Ql[ab + 8 * QST + 8];
#pragma unroll
            for (int j = 0; j < 8; j++) {
                int bb = (8 * j + g) * KST + kt * 16 + tig * 2;
                unsigned bh[2], bl[2];
                bh[0] = *(const unsigned*)&Kh[bb];
                bh[1] = *(const unsigned*)&Kh[bb + 8];
                bl[0] = *(const unsigned*)&Kl[bb];
                bl[1] = *(const unsigned*)&Kl[bb + 8];
                MMA_BF16(s[j], ah, bh);
                MMA_BF16(s[j], al, bh);
                MMA_BF16(s[j], ah, bl);
            }
        }

        bool partial = (kv0 + 64 > KV_LEN);
        float rmax0 = -1e30f, rmax1 = -1e30f;
        if (!partial) {
#pragma unroll
            for (int j = 0; j < 8; j++) {
                int col = kv0 + 8 * j + tig * 2;
                const float* mp = mask + (size_t)row0 * KV_LEN + col;
                float2 mk0 = *(const float2*)mp;
                float2 mk1 = *(const float2*)(mp + (size_t)8 * KV_LEN);
                s[j][0] = fmaf(s[j][0], ATTN_SCALE, mk0.x);
                s[j][1] = fmaf(s[j][1], ATTN_SCALE, mk0.y);
                s[j][2] = fmaf(s[j][2], ATTN_SCALE, mk1.x);
                s[j][3] = fmaf(s[j][3], ATTN_SCALE, mk1.y);
                rmax0 = fmaxf(rmax0, fmaxf(s[j][0], s[j][1]));
                rmax1 = fmaxf(rmax1, fmaxf(s[j][2], s[j][3]));
            }
        } else {
#pragma unroll
            for (int j = 0; j < 8; j++) {
#pragma unroll
                for (int c = 0; c < 2; c++) {
                    int col = kv0 + 8 * j + tig * 2 + c;
                    if (col < KV_LEN) {
                        s[j][c]     = fmaf(s[j][c], ATTN_SCALE,
                                           mask[(size_t)row0 * KV_LEN + col]);
                        s[j][2 + c] = fmaf(s[j][2 + c], ATTN_SCALE,
                                           mask[(size_t)(row0 + 8) * KV_LEN + col]);
                    } else {
                        s[j][c] = -1e30f;
                        s[j][2 + c] = -1e30f;
                    }
                }
                rmax0 = fmaxf(rmax0, fmaxf(s[j][0], s[j][1]));
                rmax1 = fmaxf(rmax1, fmaxf(s[j][2], s[j][3]));
            }
        }
        rmax0 = fmaxf(rmax0, __shfl_xor_sync(0xffffffffu, rmax0, 1));
        rmax0 = fmaxf(rmax0, __shfl_xor_sync(0xffffffffu, rmax0, 2));
        rmax1 = fmaxf(rmax1, __shfl_xor_sync(0xffffffffu, rmax1, 1));
        rmax1 = fmaxf(rmax1, __shfl_xor_sync(0xffffffffu, rmax1, 2));

        float mn0 = fmaxf(m0, rmax0), mn1 = fmaxf(m1, rmax1);
        float f0 = __expf(m0 - mn0), f1 = __expf(m1 - mn1);
        m0 = mn0; m1 = mn1;

        float sum0 = 0.f, sum1 = 0.f;
#pragma unroll
        for (int j = 0; j < 8; j++) {
            s[j][0] = __expf(s[j][0] - mn0);
            s[j][1] = __expf(s[j][1] - mn0);
            s[j][2] = __expf(s[j][2] - mn1);
            s[j][3] = __expf(s[j][3] - mn1);
            sum0 += s[j][0] + s[j][1];
            sum1 += s[j][2] + s[j][3];
        }
        sum0 += __shfl_xor_sync(0xffffffffu, sum0, 1);
        sum0 += __shfl_xor_sync(0xffffffffu, sum0, 2);
        sum1 += __shfl_xor_sync(0xffffffffu, sum1, 1);
        sum1 += __shfl_xor_sync(0xffffffffu, sum1, 2);
        l0 = l0 * f0 + sum0;
        l1 = l1 * f1 + sum1;

#pragma unroll
        for (int n = 0; n < 16; n++) {
            o[n][0] *= f0; o[n][1] *= f0; o[n][2] *= f1; o[n][3] *= f1;
        }

#pragma unroll
        for (int t = 0; t < 4; t++) {
            unsigned ph[4], pl[4];
            split2(s[2 * t][0],     s[2 * t][1],     ph[0], pl[0]);
            split2(s[2 * t][2],     s[2 * t][3],     ph[1], pl[1]);
            split2(s[2 * t + 1][0], s[2 * t + 1][1], ph[2], pl[2]);
            split2(s[2 * t + 1][2], s[2 * t + 1][3], ph[3], pl[3]);
#pragma unroll
            for (int n = 0; n < 16; n++) {
                int vb = (8 * n + g) * VST + t * 16 + tig * 2;
                unsigned bh[2], bl[2];
                bh[0] = *(const unsigned*)&Vh[vb];
                bh[1] = *(const unsigned*)&Vh[vb + 8];
                bl[0] = *(const unsigned*)&Vl[vb];
                bl[1] = *(const unsigned*)&Vl[vb + 8];
                MMA_BF16(o[n], ph, bh);
                MMA_BF16(o[n], pl, bh);
                MMA_BF16(o[n], ph, bl);
            }
        }
    }

    float il0 = 1.f / l0, il1 = 1.f / l1;
#pragma unroll
    for (int n = 0; n < 16; n++) {
        unsigned h01, lo01, h23, lo23;
        split2(o[n][0] * il0, o[n][1] * il0, h01, lo01);
        split2(o[n][2] * il1, o[n][3] * il1, h23, lo23);
        size_t base = (size_t)row0 * HIDDEN + h * HD + 8 * n + tig * 2;
        *(unsigned*)(g_attnhi + base) = h01;
        *(unsigned*)(g_attnlo + base) = lo01;
        *(unsigned*)(g_attnhi + base + (size_t)8 * HIDDEN) = h23;
        *(unsigned*)(g_attnlo + base + (size_t)8 * HIDDEN) = lo23;
    }
}

// ---------------------------------------------------------------------------
extern "C" void kernel_launch(void* const* d_in, const int* in_sizes, int n_in,
                              void* d_out, int out_size)
{
    const float* hidden = (const float*)d_in[0];
    const float* cross  = (const float*)d_in[1];
    const float* mask   = (const float*)d_in[2];
    const float* w_qkv  = (const float*)d_in[3];
    const float* w_o    = (const float*)d_in[4];
    const float* q_norm = (const float*)d_in[5];
    const float* k_norm = (const float*)d_in[6];
    float* out = (float*)d_out;
    (void)in_sizes; (void)n_in; (void)out_size;

    float *pq, *pkv;
    cudaGetSymbolAddress((void**)&pq,  g_q);
    cudaGetSymbolAddress((void**)&pkv, g_kv);
    __nv_bfloat16 *hid_hi, *hid_lo, *cross_hi, *cross_lo;
    __nv_bfloat16 *wqkvT_hi, *wqkvT_lo, *woT_hi, *woT_lo;
    __nv_bfloat16 *qhi, *qlo, *khi, *klo, *attnhi, *attnlo;
    cudaGetSymbolAddress((void**)&hid_hi,   g_hid_hi);
    cudaGetSymbolAddress((void**)&hid_lo,   g_hid_lo);
    cudaGetSymbolAddress((void**)&cross_hi, g_cross_hi);
    cudaGetSymbolAddress((void**)&cross_lo, g_cross_lo);
    cudaGetSymbolAddress((void**)&wqkvT_hi, g_wqkvT_hi);
    cudaGetSymbolAddress((void**)&wqkvT_lo, g_wqkvT_lo);
    cudaGetSymbolAddress((void**)&woT_hi,   g_woT_hi);
    cudaGetSymbolAddress((void**)&woT_lo,   g_woT_lo);
    cudaGetSymbolAddress((void**)&qhi,      g_qhi);
    cudaGetSymbolAddress((void**)&qlo,      g_qlo);
    cudaGetSymbolAddress((void**)&khi,      g_khi);
    cudaGetSymbolAddress((void**)&klo,      g_klo);
    cudaGetSymbolAddress((void**)&attnhi,   g_attnhi);
    cudaGetSymbolAddress((void**)&attnlo,   g_attnlo);

    // 1) fused activation split
    {
        int n4 = (Q_LEN + KV_LEN) * HIDDEN / 4;
        split_acts<<<(n4 + 255) / 256, 256>>>(hidden, cross);
    }
    // 2,3) weight transpose + split
    wtrans_split<<<dim3(QKV_LDB / 32, HIDDEN / 32), dim3(32, 8)>>>(
        w_qkv, wqkvT_hi, wqkvT_lo, HIDDEN, QKV_LDB);
    wtrans_split<<<dim3(HIDDEN / 32, HIDDEN / 32), dim3(32, 8)>>>(
        w_o, woT_hi, woT_lo, HIDDEN, HIDDEN);

    cudaFuncSetAttribute(gemm_bf16x3, cudaFuncAttributeMaxDynamicSharedMemorySize,
                         GB_SMEM);

    // 4) KV projection (profiled launch): M=6404, N=2048
    gemm_bf16x3<<<dim3(KV_N / 128, (KV_LEN + 127) / 128), 256, GB_SMEM>>>(
        cross_hi, cross_lo,
        wqkvT_hi + (size_t)(NH * HD) * HIDDEN, wqkvT_lo + (size_t)(NH * HD) * HIDDEN,
        pkv, KV_LEN, KV_N);
    // 5) Q projection: M=1024, N=4096
    gemm_bf16x3<<<dim3(HIDDEN / 128, Q_LEN / 128), 256, GB_SMEM>>>(
        hid_hi, hid_lo, wqkvT_hi, wqkvT_lo, pq, Q_LEN, HIDDEN);

    // 6,7) RMS norms -> bf16 hi/lo
    {
        int nwarps = Q_LEN * NH;
        rmsnorm_split<<<(nwarps * 32 + 255) / 256, 256>>>(
            pq, q_norm, qhi, qlo, Q_LEN, NH, HIDDEN, HIDDEN);
        nwarps = KV_LEN * NKVH;
        rmsnorm_split<<<(nwarps * 32 + 255) / 256, 256>>>(
            pkv, k_norm, khi, klo, KV_LEN, NKVH, KV_N, NKVH * HD);
    }
    // 8) V transpose + split
    vtrans_split<<<dim3(KV_PAD / 32, HD / 32, NKVH), dim3(32, 8)>>>(pkv);

    // 9) attention
    cudaFuncSetAttribute(attn_mma, cudaFuncAttributeMaxDynamicSharedMemorySize,
                         ATTN_SMEM);
    attn_mma<<<dim3(Q_LEN / 128, NH), 256, ATTN_SMEM>>>(mask);

    // 10) O projection: M=1024, N=4096
    gemm_bf16x3<<<dim3(HIDDEN / 128, Q_LEN / 128), 256, GB_SMEM>>>(
        attnhi, attnlo, woT_hi, woT_lo, out, Q_LEN, HIDDEN);
}

// round 11
// speedup vs baseline: 2.4965x; 1.0041x over previous
#include <cuda_runtime.h>
#include <cuda_bf16.h>
#include <stdint.h>
#include <math.h>

#define Q_LEN   1024
#define KV_LEN  6404
#define KV_PAD  6464
#define HIDDEN  4096
#define NH      32
#define NKVH    8
#define HD      128
#define QKV_LDB 6144
#define KV_N    2048
#define ATTN_SCALE 0.08838834764831845f

// ---------------- scratch ----------------
__device__ float g_q[Q_LEN * HIDDEN];
__device__ float g_kv[KV_LEN * KV_N];

__device__ __nv_bfloat16 g_hid_hi[Q_LEN * HIDDEN];
__device__ __nv_bfloat16 g_hid_lo[Q_LEN * HIDDEN];
__device__ __nv_bfloat16 g_cross_hi[KV_LEN * HIDDEN];
__device__ __nv_bfloat16 g_cross_lo[KV_LEN * HIDDEN];
__device__ __nv_bfloat16 g_wqkvT_hi[QKV_LDB * HIDDEN];   // [col][k]
__device__ __nv_bfloat16 g_wqkvT_lo[QKV_LDB * HIDDEN];
__device__ __nv_bfloat16 g_woT_hi[HIDDEN * HIDDEN];
__device__ __nv_bfloat16 g_woT_lo[HIDDEN * HIDDEN];
__device__ __nv_bfloat16 g_qhi[Q_LEN * HIDDEN];
__device__ __nv_bfloat16 g_qlo[Q_LEN * HIDDEN];
__device__ __nv_bfloat16 g_khi[KV_LEN * (NKVH * HD)];
__device__ __nv_bfloat16 g_klo[KV_LEN * (NKVH * HD)];
__device__ __nv_bfloat16 g_vthi[NKVH * HD * KV_PAD];
__device__ __nv_bfloat16 g_vtlo[NKVH * HD * KV_PAD];
__device__ __nv_bfloat16 g_attnhi[Q_LEN * HIDDEN];
__device__ __nv_bfloat16 g_attnlo[Q_LEN * HIDDEN];

__device__ __forceinline__ void split2(float x, float y, unsigned& hi, unsigned& lo)
{
    __nv_bfloat16 hx = __float2bfloat16(x), hy = __float2bfloat16(y);
    float lx = x - __bfloat162float(hx), ly = y - __bfloat162float(hy);
    __nv_bfloat16 lxb = __float2bfloat16(lx), lyb = __float2bfloat16(ly);
    hi = (unsigned)__bfloat16_as_ushort(hx) | ((unsigned)__bfloat16_as_ushort(hy) << 16);
    lo = (unsigned)__bfloat16_as_ushort(lxb) | ((unsigned)__bfloat16_as_ushort(lyb) << 16);
}

__device__ __forceinline__ uint32_t smem_u32(const void* p)
{
    uint32_t a;
    asm("{ .reg .u64 t; cvta.to.shared.u64 t, %1; cvt.u32.u64 %0, t; }"
        : "=r"(a) : "l"(p));
    return a;
}
#define CP16(dst, src, n) \
    asm volatile("cp.async.cg.shared.global [%0], [%1], 16, %2;" \
                 :: "r"(dst), "l"(src), "r"(n))
#define CP_COMMIT() asm volatile("cp.async.commit_group;" ::: "memory")
#define CP_WAIT1()  asm volatile("cp.async.wait_group 1;" ::: "memory")

#define MMA_BF16(d, a, b)                                                      \
    asm volatile(                                                              \
        "mma.sync.aligned.m16n8k16.row.col.f32.bf16.bf16.f32 "                 \
        "{%0,%1,%2,%3},{%4,%5,%6,%7},{%8,%9},{%0,%1,%2,%3};"                   \
        : "+f"((d)[0]), "+f"((d)[1]), "+f"((d)[2]), "+f"((d)[3])               \
        : "r"((a)[0]), "r"((a)[1]), "r"((a)[2]), "r"((a)[3]),                  \
          "r"((b)[0]), "r"((b)[1]))

#define LDSM4(r, addr)                                                         \
    asm volatile(                                                              \
        "ldmatrix.sync.aligned.m8n8.x4.shared.b16 {%0,%1,%2,%3}, [%4];"        \
        : "=r"((r)[0]), "=r"((r)[1]), "=r"((r)[2]), "=r"((r)[3])               \
        : "r"(addr))

// ---------------- pipelined bf16x3 GEMM with ldmatrix fragments --------------
// block 128x128, BK=64 halves (128B rows, SW128 xor swizzle), 256 threads,
// 3-stage cp.async ring.
#define GB_BUF   (128 * 128)           // one tile buffer (bytes)
#define GB_STAGE (4 * GB_BUF)          // Ah, Al, Bh, Bl = 64KB
#define GB_NST   3
#define GB_SMEM  (GB_NST * GB_STAGE)   // 192KB

__global__ void __launch_bounds__(256, 1) gemm_bf16x3(
    const __nv_bfloat16* __restrict__ Ahi, const __nv_bfloat16* __restrict__ Alo,
    const __nv_bfloat16* __restrict__ Bthi, const __nv_bfloat16* __restrict__ Btlo,
    float* __restrict__ C, int M, int ldc)
{
    extern __shared__ char smg[];
    const uint32_t sb = smem_u32(smg);
    const int tid  = threadIdx.x;
    const int warp = tid >> 5, lane = tid & 31;
    const int g = lane >> 2, tig = lane & 3;
    const int wm = warp & 1, wn = warp >> 1;
    const int row0 = blockIdx.y * 128, col0 = blockIdx.x * 128;
    const int rowbase = wm * 64, colbase = wn * 32;
    const int K = HIDDEN;
    const int nck = K / 64;

    // ldmatrix per-lane addressing (within a stage buffer):
    // A (am tile): row = rowbase + am*16 + (lane&15); chunk = 2ks + (lane>>4)
    const int a_row_in = lane & 15;
    const int a_ckb    = lane >> 4;         // 0/1
    // B (pair p covers an=2p,2p+1): row = colbase + p*16 + ((lane>>4)&1)*8 + (lane&7)
    //                               chunk = 2ks + ((lane>>3)&1)
    const int b_row_in = (((lane >> 4) & 1) << 3) + (lane & 7);
    const int b_ckb    = (lane >> 3) & 1;

    float acc[4][4][4];
#pragma unroll
    for (int i = 0; i < 4; i++)
#pragma unroll
        for (int j = 0; j < 4; j++)
#pragma unroll
            for (int t = 0; t < 4; t++) acc[i][j][t] = 0.f;

    auto load_chunk = [&](int ck, int st) {
        const uint32_t stb = sb + st * GB_STAGE;
        const int k0 = ck * 64;                 // halves
#pragma unroll
        for (int i = 0; i < 4; i++) {
            int idx = tid + i * 256;            // 0..1023
            int r = idx >> 3, c = idx & 7;      // 128 rows x 8 chunks of 16B
            uint32_t soff = (uint32_t)(r * 128 + ((c ^ (r & 7)) * 16));
            int gr = row0 + r;
            int ok = (gr < M) ? 16 : 0;
            int grc = (gr < M) ? gr : 0;
            size_t aoff = (size_t)grc * K + k0 + c * 8;
            CP16(stb + 0 * GB_BUF + soff, Ahi + aoff, ok);
            CP16(stb + 1 * GB_BUF + soff, Alo + aoff, ok);
            size_t boff = (size_t)(col0 + r) * K + k0 + c * 8;
            CP16(stb + 2 * GB_BUF + soff, Bthi + boff, 16);
            CP16(stb + 3 * GB_BUF + soff, Btlo + boff, 16);
        }
    };

    load_chunk(0, 0); CP_COMMIT();
    load_chunk(1, 1); CP_COMMIT();

    for (int ck = 0; ck < nck; ck++) {
        const int st = ck % GB_NST;
        CP_WAIT1();
        __syncthreads();
        if (ck + 2 < nck) load_chunk(ck + 2, (ck + 2) % GB_NST);
        CP_COMMIT();

        const uint32_t stb = sb + st * GB_STAGE;

#pragma unroll
        for (int ks = 0; ks < 4; ks++) {
            unsigned ah[4][4], al[4][4], bfr[2][4];
            // A fragments via ldmatrix.x4 (m0/m1 = k-chunk0 rows 0-15, m2/m3 = chunk1)
#pragma unroll
            for (int am = 0; am < 4; am++) {
                int row = rowbase + am * 16 + a_row_in;
                int ck4 = (2 * ks + a_ckb) ^ (row & 7);
                uint32_t addr = stb + (uint32_t)(row * 128 + ck4 * 16);
                LDSM4(ah[am], addr);
                LDSM4(al[am], addr + GB_BUF);
            }
            // B fragments: pair p covers an=2p, 2p+1 (regs: b[2p][0],b[2p][1],b[2p+1][0],b[2p+1][1])
            unsigned bh[4][2], bl[4][2];
#pragma unroll
            for (int p = 0; p < 2; p++) {
                int row = colbase + p * 16 + b_row_in;
                int ck4 = (2 * ks + b_ckb) ^ (row & 7);
                uint32_t addr = stb + 2 * GB_BUF + (uint32_t)(row * 128 + ck4 * 16);
                LDSM4(bfr[0], addr);
                LDSM4(bfr[1], addr + GB_BUF);
                bh[2 * p][0] = bfr[0][0]; bh[2 * p][1] = bfr[0][1];
                bh[2 * p + 1][0] = bfr[0][2]; bh[2 * p + 1][1] = bfr[0][3];
                bl[2 * p][0] = bfr[1][0]; bl[2 * p][1] = bfr[1][1];
                bl[2 * p + 1][0] = bfr[1][2]; bl[2 * p + 1][1] = bfr[1][3];
            }
#pragma unroll
            for (int am = 0; am < 4; am++)
#pragma unroll
                for (int an = 0; an < 4; an++) MMA_BF16(acc[am][an], ah[am], bh[an]);
#pragma unroll
            for (int am = 0; am < 4; am++)
#pragma unroll
                for (int an = 0; an < 4; an++) MMA_BF16(acc[am][an], al[am], bh[an]);
#pragma unroll
            for (int am = 0; am < 4; am++)
#pragma unroll
                for (int an = 0; an < 4; an++) MMA_BF16(acc[am][an], ah[am], bl[an]);
        }
        __syncthreads();
    }

    // ---- epilogue ----
#pragma unroll
    for (int am = 0; am < 4; am++) {
#pragma unroll
        for (int an = 0; an < 4; an++) {
            int r = row0 + rowbase + am * 16 + g;
            int c = col0 + colbase + an * 8 + tig * 2;
            if (r < M)
                *(float2*)(C + (size_t)r * ldc + c) =
                    make_float2(acc[am][an][0], acc[am][an][1]);
            if (r + 8 < M)
                *(float2*)(C + (size_t)(r + 8) * ldc + c) =
                    make_float2(acc[am][an][2], acc[am][an][3]);
        }
    }
}

// ---------------- fused fp32 -> bf16 hi/lo split of both activations ---------
__global__ void split_acts(const float* __restrict__ hid, const float* __restrict__ cross)
{
    const int nh = Q_LEN * HIDDEN / 4;
    const int nc = KV_LEN * HIDDEN / 4;
    int i = blockIdx.x * blockDim.x + threadIdx.x;
    if (i >= nh + nc) return;
    const float4* src;
    __nv_bfloat16 *hi, *lo;
    int j;
    if (i < nh) { src = (const float4*)hid;   hi = g_hid_hi;   lo = g_hid_lo;   j = i; }
    else        { src = (const float4*)cross; hi = g_cross_hi; lo = g_cross_lo; j = i - nh; }
    float4 v = src[j];
    uint2 uh, ul;
    split2(v.x, v.y, uh.x, ul.x);
    split2(v.z, v.w, uh.y, ul.y);
    ((uint2*)hi)[j] = uh;
    ((uint2*)lo)[j] = ul;
}

// ---------------- fp32 [R][C] -> bf16 hi/lo [C][R] ----------------
__global__ void wtrans_split(const float* __restrict__ w,
                             __nv_bfloat16* __restrict__ hi,
                             __nv_bfloat16* __restrict__ lo, int R, int C)
{
    __shared__ float t[32][33];
    int tx = threadIdx.x, ty = threadIdx.y;
    int r0 = blockIdx.y * 32, c0 = blockIdx.x * 32;
#pragma unroll
    for (int i = 0; i < 4; i++)
        t[ty + 8 * i][tx] = w[(size_t)(r0 + ty + 8 * i) * C + c0 + tx];
    __syncthreads();
#pragma unroll
    for (int i = 0; i < 4; i++) {
        float v = t[tx][ty + 8 * i];
        __nv_bfloat16 hb = __float2bfloat16(v);
        __nv_bfloat16 lb = __float2bfloat16(v - __bfloat162float(hb));
        size_t off = (size_t)(c0 + ty + 8 * i) * R + r0 + tx;
        hi[off] = hb; lo[off] = lb;
    }
}

// ---------------- V transpose+split ----------------
__global__ void vtrans_split(const float* __restrict__ kv)
{
    __shared__ float t[32][33];
    int tx = threadIdx.x, ty = threadIdx.y;
    int kv0 = blockIdx.x * 32, d0 = blockIdx.y * 32, kvh = blockIdx.z;
#pragma unroll
    for (int i = 0; i < 4; i++) {
        int r = kv0 + ty + 8 * i;
        t[ty + 8 * i][tx] = (r < KV_LEN)
            ? kv[(size_t)r * KV_N + NKVH * HD + kvh * HD + d0 + tx] : 0.f;
    }
    __syncthreads();
#pragma unroll
    for (int i = 0; i < 4; i++) {
        float v = t[tx][ty + 8 * i];
        __nv_bfloat16 hb = __float2bfloat16(v);
        __nv_bfloat16 lb = __float2bfloat16(v - __bfloat162float(hb));
        size_t off = (size_t)(kvh * HD + d0 + ty + 8 * i) * KV_PAD + kv0 + tx;
        g_vthi[off] = hb; g_vtlo[off] = lb;
    }
}

// ---------------- RMS norm fp32 -> bf16 hi/lo ----------------
__global__ void rmsnorm_split(const float* __restrict__ x, const float* __restrict__ w,
                              __nv_bfloat16* __restrict__ hi, __nv_bfloat16* __restrict__ lo,
                              int nrows, int nheads, int ld_in, int ld_out)
{
    int gw = (int)((blockIdx.x * blockDim.x + threadIdx.x) >> 5);
    int lane = threadIdx.x & 31;
    if (gw >= nrows * nheads) return;
    int row = gw / nheads, h = gw - row * nheads;
    const float* p = x + (size_t)row * ld_in + h * HD;
    float4 v = *(const float4*)(p + lane * 4);
    float ss = v.x * v.x + v.y * v.y + v.z * v.z + v.w * v.w;
#pragma unroll
    for (int o = 16; o > 0; o >>= 1) ss += __shfl_xor_sync(0xffffffffu, ss, o);
    float s = rsqrtf(ss * (1.f / HD) + 1e-5f);
    float4 wv = *(const float4*)(w + lane * 4);
    v.x *= s * wv.x; v.y *= s * wv.y; v.z *= s * wv.z; v.w *= s * wv.w;
    uint2 uh, ul;
    split2(v.x, v.y, uh.x, ul.x);
    split2(v.z, v.w, uh.y, ul.y);
    size_t off = (size_t)row * ld_out + h * HD + lane * 4;
    *(uint2*)(hi + off) = uh;
    *(uint2*)(lo + off) = ul;
}

// ---------------- mma.sync flash attention (unchanged) ----------------
#define QST 136
#define KST 136
#define VST 72
#define ATTN_SMEM ((2*128*QST + 2*64*KST + 2*128*VST) * 2)

__global__ void __launch_bounds__(256, 1) attn_mma(const float* __restrict__ mask)
{
    extern __shared__ __nv_bfloat16 sm[];
    __nv_bfloat16* Qh = sm;
    __nv_bfloat16* Ql = Qh + 128 * QST;
    __nv_bfloat16* Kh = Ql + 128 * QST;
    __nv_bfloat16* Kl = Kh + 64 * KST;
    __nv_bfloat16* Vh = Kl + 64 * KST;
    __nv_bfloat16* Vl = Vh + 128 * VST;

    const int tid = threadIdx.x, warp = tid >> 5, lane = tid & 31;
    const int g = lane >> 2, tig = lane & 3;
    const int h = blockIdx.y, kvh = h >> 2;
    const int q0 = blockIdx.x * 128;
    const int wr = warp * 16;
    const int row0 = q0 + wr + g;

#pragma unroll
    for (int it = 0; it < 8; it++) {
        int idx = tid + it * 256;
        int r = idx >> 4, c = (idx & 15) * 8;
        size_t off = (size_t)(q0 + r) * HIDDEN + h * HD + c;
        *(uint4*)&Qh[r * QST + c] = *(const uint4*)(g_qhi + off);
        *(uint4*)&Ql[r * QST + c] = *(const uint4*)(g_qlo + off);
    }

    float o[16][4];
#pragma unroll
    for (int n = 0; n < 16; n++)
#pragma unroll
        for (int t = 0; t < 4; t++) o[n][t] = 0.f;
    float m0 = -1e30f, m1 = -1e30f, l0 = 0.f, l1 = 0.f;

    for (int kv0 = 0; kv0 < KV_LEN; kv0 += 64) {
        __syncthreads();
#pragma unroll
        for (int it = 0; it < 4; it++) {
            int idx = tid + it * 256;
            int r = idx >> 4, c = (idx & 15) * 8;
            uint4 vh = make_uint4(0, 0, 0, 0), vl = vh;
            if (kv0 + r < KV_LEN) {
                size_t off = (size_t)(kv0 + r) * (NKVH * HD) + kvh * HD + c;
                vh = *(const uint4*)(g_khi + off);
                vl = *(const uint4*)(g_klo + off);
            }
            *(uint4*)&Kh[r * KST + c] = vh;
            *(uint4*)&Kl[r * KST + c] = vl;
        }
#pragma unroll
        for (int it = 0; it < 4; it++) {
            int idx = tid + it * 256;
            int d = idx >> 3, c = (idx & 7) * 8;
            size_t off = ((size_t)kvh * HD + d) * KV_PAD + kv0 + c;
            *(uint4*)&Vh[d * VST + c] = *(const uint4*)(g_vthi + off);
            *(uint4*)&Vl[d * VST + c] = *(const uint4*)(g_vtlo + off);
        }
        __syncthreads();

        float s[8][4];
#pragma unroll
        for (int j = 0; j < 8; j++)
#pragma unroll
            for (int c = 0; c < 4; c++) s[j][c] = 0.f;

#pragma unroll
        for (int kt = 0; kt < 8; kt++) {
            int ab = (wr + g) * QST + kt * 16 + tig * 2;
            unsigned ah[4], al[4];
            ah[0] = *(const unsigned*)&Qh[ab];
            ah[1] = *(const unsigned*)&Qh[ab + 8 * QST];
            ah[2] = *(const unsigned*)&Qh[ab + 8];
            ah[3] = *(const unsigned*)&Qh[ab + 8 * QST + 8];
            al[0] = *(const unsigned*)&Ql[ab];
            al[1] = *(const unsigned*)&Ql[ab + 8 * QST];
            al[2] = *(const unsigned*)&Ql[ab + 8];
            al[3] = *(const unsigned*)&Ql[ab + 8 * QST + 8];
#pragma unroll
            for (int j = 0; j < 8; j++) {
                int bb = (8 * j + g) * KST + kt * 16 + tig * 2;
                unsigned bh[2], bl[2];
                bh[0] = *(const unsigned*)&Kh[bb];
                bh[1] = *(const unsigned*)&Kh[bb + 8];
                bl[0] = *(const unsigned*)&Kl[bb];
                bl[1] = *(const unsigned*)&Kl[bb + 8];
                MMA_BF16(s[j], ah, bh);
                MMA_BF16(s[j], al, bh);
                MMA_BF16(s[j], ah, bl);
            }
        }

        bool partial = (kv0 + 64 > KV_LEN);
        float rmax0 = -1e30f, rmax1 = -1e30f;
        if (!partial) {
#pragma unroll
            for (int j = 0; j < 8; j++) {
                int col = kv0 + 8 * j + tig * 2;
                const float* mp = mask + (size_t)row0 * KV_LEN + col;
                float2 mk0 = *(const float2*)mp;
                float2 mk1 = *(const float2*)(mp + (size_t)8 * KV_LEN);
                s[j][0] = fmaf(s[j][0], ATTN_SCALE, mk0.x);
                s[j][1] = fmaf(s[j][1], ATTN_SCALE, mk0.y);
                s[j][2] = fmaf(s[j][2], ATTN_SCALE, mk1.x);
                s[j][3] = fmaf(s[j][3], ATTN_SCALE, mk1.y);
                rmax0 = fmaxf(rmax0, fmaxf(s[j][0], s[j][1]));
                rmax1 = fmaxf(rmax1, fmaxf(s[j][2], s[j][3]));
            }
        } else {
#pragma unroll
            for (int j = 0; j < 8; j++) {
#pragma unroll
                for (int c = 0; c < 2; c++) {
                    int col = kv0 + 8 * j + tig * 2 + c;
                    if (col < KV_LEN) {
                        s[j][c]     = fmaf(s[j][c], ATTN_SCALE,
                                           mask[(size_t)row0 * KV_LEN + col]);
                        s[j][2 + c] = fmaf(s[j][2 + c], ATTN_SCALE,
                                           mask[(size_t)(row0 + 8) * KV_LEN + col]);
                    } else {
                        s[j][c] = -1e30f;
                        s[j][2 + c] = -1e30f;
                    }
                }
                rmax0 = fmaxf(rmax0, fmaxf(s[j][0], s[j][1]));
                rmax1 = fmaxf(rmax1, fmaxf(s[j][2], s[j][3]));
            }
        }
        rmax0 = fmaxf(rmax0, __shfl_xor_sync(0xffffffffu, rmax0, 1));
        rmax0 = fmaxf(rmax0, __shfl_xor_sync(0xffffffffu, rmax0, 2));
        rmax1 = fmaxf(rmax1, __shfl_xor_sync(0xffffffffu, rmax1, 1));
        rmax1 = fmaxf(rmax1, __shfl_xor_sync(0xffffffffu, rmax1, 2));

        float mn0 = fmaxf(m0, rmax0), mn1 = fmaxf(m1, rmax1);
        float f0 = __expf(m0 - mn0), f1 = __expf(m1 - mn1);
        m0 = mn0; m1 = mn1;

        float sum0 = 0.f, sum1 = 0.f;
#pragma unroll
        for (int j = 0; j < 8; j++) {
            s[j][0] = __expf(s[j][0] - mn0);
            s[j][1] = __expf(s[j][1] - mn0);
            s[j][2] = __expf(s[j][2] - mn1);
            s[j][3] = __expf(s[j][3] - mn1);
            sum0 += s[j][0] + s[j][1];
            sum1 += s[j][2] + s[j][3];
        }
        sum0 += __shfl_xor_sync(0xffffffffu, sum0, 1);
        sum0 += __shfl_xor_sync(0xffffffffu, sum0, 2);
        sum1 += __shfl_xor_sync(0xffffffffu, sum1, 1);
        sum1 += __shfl_xor_sync(0xffffffffu, sum1, 2);
        l0 = l0 * f0 + sum0;
        l1 = l1 * f1 + sum1;

#pragma unroll
        for (int n = 0; n < 16; n++) {
            o[n][0] *= f0; o[n][1] *= f0; o[n][2] *= f1; o[n][3] *= f1;
        }

#pragma unroll
        for (int t = 0; t < 4; t++) {
            unsigned ph[4], pl[4];
            split2(s[2 * t][0],     s[2 * t][1],     ph[0], pl[0]);
            split2(s[2 * t][2],     s[2 * t][3],     ph[1], pl[1]);
            split2(s[2 * t + 1][0], s[2 * t + 1][1], ph[2], pl[2]);
            split2(s[2 * t + 1][2], s[2 * t + 1][3], ph[3], pl[3]);
#pragma unroll
            for (int n = 0; n < 16; n++) {
                int vb = (8 * n + g) * VST + t * 16 + tig * 2;
                unsigned bh[2], bl[2];
                bh[0] = *(const unsigned*)&Vh[vb];
                bh[1] = *(const unsigned*)&Vh[vb + 8];
                bl[0] = *(const unsigned*)&Vl[vb];
                bl[1] = *(const unsigned*)&Vl[vb + 8];
                MMA_BF16(o[n], ph, bh);
                MMA_BF16(o[n], pl, bh);
                MMA_BF16(o[n], ph, bl);
            }
        }
    }

    float il0 = 1.f / l0, il1 = 1.f / l1;
#pragma unroll
    for (int n = 0; n < 16; n++) {
        unsigned h01, lo01, h23, lo23;
        split2(o[n][0] * il0, o[n][1] * il0, h01, lo01);
        split2(o[n][2] * il1, o[n][3] * il1, h23, lo23);
        size_t base = (size_t)row0 * HIDDEN + h * HD + 8 * n + tig * 2;
        *(unsigned*)(g_attnhi + base) = h01;
        *(unsigned*)(g_attnlo + base) = lo01;
        *(unsigned*)(g_attnhi + base + (size_t)8 * HIDDEN) = h23;
        *(unsigned*)(g_attnlo + base + (size_t)8 * HIDDEN) = lo23;
    }
}

// ---------------------------------------------------------------------------
extern "C" void kernel_launch(void* const* d_in, const int* in_sizes, int n_in,
                              void* d_out, int out_size)
{
    const float* hidden = (const float*)d_in[0];
    const float* cross  = (const float*)d_in[1];
    const float* mask   = (const float*)d_in[2];
    const float* w_qkv  = (const float*)d_in[3];
    const float* w_o    = (const float*)d_in[4];
    const float* q_norm = (const float*)d_in[5];
    const float* k_norm = (const float*)d_in[6];
    float* out = (float*)d_out;
    (void)in_sizes; (void)n_in; (void)out_size;

    float *pq, *pkv;
    cudaGetSymbolAddress((void**)&pq,  g_q);
    cudaGetSymbolAddress((void**)&pkv, g_kv);
    __nv_bfloat16 *hid_hi, *hid_lo, *cross_hi, *cross_lo;
    __nv_bfloat16 *wqkvT_hi, *wqkvT_lo, *woT_hi, *woT_lo;
    __nv_bfloat16 *qhi, *qlo, *khi, *klo, *attnhi, *attnlo;
    cudaGetSymbolAddress((void**)&hid_hi,   g_hid_hi);
    cudaGetSymbolAddress((void**)&hid_lo,   g_hid_lo);
    cudaGetSymbolAddress((void**)&cross_hi, g_cross_hi);
    cudaGetSymbolAddress((void**)&cross_lo, g_cross_lo);
    cudaGetSymbolAddress((void**)&wqkvT_hi, g_wqkvT_hi);
    cudaGetSymbolAddress((void**)&wqkvT_lo, g_wqkvT_lo);
    cudaGetSymbolAddress((void**)&woT_hi,   g_woT_hi);
    cudaGetSymbolAddress((void**)&woT_lo,   g_woT_lo);
    cudaGetSymbolAddress((void**)&qhi,      g_qhi);
    cudaGetSymbolAddress((void**)&qlo,      g_qlo);
    cudaGetSymbolAddress((void**)&khi,      g_khi);
    cudaGetSymbolAddress((void**)&klo,      g_klo);
    cudaGetSymbolAddress((void**)&attnhi,   g_attnhi);
    cudaGetSymbolAddress((void**)&attnlo,   g_attnlo);

    // 1) fused activation split
    {
        int n4 = (Q_LEN + KV_LEN) * HIDDEN / 4;
        split_acts<<<(n4 + 255) / 256, 256>>>(hidden, cross);
    }
    // 2,3) weight transpose + split
    wtrans_split<<<dim3(QKV_LDB / 32, HIDDEN / 32), dim3(32, 8)>>>(
        w_qkv, wqkvT_hi, wqkvT_lo, HIDDEN, QKV_LDB);
    wtrans_split<<<dim3(HIDDEN / 32, HIDDEN / 32), dim3(32, 8)>>>(
        w_o, woT_hi, woT_lo, HIDDEN, HIDDEN);

    cudaFuncSetAttribute(gemm_bf16x3, cudaFuncAttributeMaxDynamicSharedMemorySize,
                         GB_SMEM);

    // 4) KV projection (profiled launch): M=6404, N=2048
    gemm_bf16x3<<<dim3(KV_N / 128, (KV_LEN + 127) / 128), 256, GB_SMEM>>>(
        cross_hi, cross_lo,
        wqkvT_hi + (size_t)(NH * HD) * HIDDEN, wqkvT_lo + (size_t)(NH * HD) * HIDDEN,
        pkv, KV_LEN, KV_N);
    // 5) Q projection: M=1024, N=4096
    gemm_bf16x3<<<dim3(HIDDEN / 128, Q_LEN / 128), 256, GB_SMEM>>>(
        hid_hi, hid_lo, wqkvT_hi, wqkvT_lo, pq, Q_LEN, HIDDEN);

    // 6,7) RMS norms -> bf16 hi/lo
    {
        int nwarps = Q_LEN * NH;
        rmsnorm_split<<<(nwarps * 32 + 255) / 256, 256>>>(
            pq, q_norm, qhi, qlo, Q_LEN, NH, HIDDEN, HIDDEN);
        nwarps = KV_LEN * NKVH;
        rmsnorm_split<<<(nwarps * 32 + 255) / 256, 256>>>(
            pkv, k_norm, khi, klo, KV_LEN, NKVH, KV_N, NKVH * HD);
    }
    // 8) V transpose + split
    vtrans_split<<<dim3(KV_PAD / 32, HD / 32, NKVH), dim3(32, 8)>>>(pkv);

    // 9) attention
    cudaFuncSetAttribute(attn_mma, cudaFuncAttributeMaxDynamicSharedMemorySize,
                         ATTN_SMEM);
    attn_mma<<<dim3(Q_LEN / 128, NH), 256, ATTN_SMEM>>>(mask);

    // 10) O projection: M=1024, N=4096
    gemm_bf16x3<<<dim3(HIDDEN / 128, Q_LEN / 128), 256, GB_SMEM>>>(
        attnhi, attnlo, woT_hi, woT_lo, out, Q_LEN, HIDDEN);
}

// round 12
// speedup vs baseline: 2.6071x; 1.0443x over previous
#include <cuda_runtime.h>
#include <cuda_bf16.h>
#include <stdint.h>
#include <math.h>

#define Q_LEN   1024
#define KV_LEN  6404
#define KV_PAD  6464
#define HIDDEN  4096
#define NH      32
#define NKVH    8
#define HD      128
#define QKV_LDB 6144
#define KV_N    2048
#define ATTN_SCALE 0.08838834764831845f

// ---------------- scratch ----------------
__device__ float g_q[Q_LEN * HIDDEN];
__device__ float g_kv[KV_LEN * KV_N];

__device__ __nv_bfloat16 g_hid_hi[Q_LEN * HIDDEN];
__device__ __nv_bfloat16 g_hid_lo[Q_LEN * HIDDEN];
__device__ __nv_bfloat16 g_cross_hi[KV_LEN * HIDDEN];
__device__ __nv_bfloat16 g_cross_lo[KV_LEN * HIDDEN];
__device__ __nv_bfloat16 g_wqkvT_hi[QKV_LDB * HIDDEN];   // [col][k]
__device__ __nv_bfloat16 g_wqkvT_lo[QKV_LDB * HIDDEN];
__device__ __nv_bfloat16 g_woT_hi[HIDDEN * HIDDEN];
__device__ __nv_bfloat16 g_woT_lo[HIDDEN * HIDDEN];
__device__ __nv_bfloat16 g_qhi[Q_LEN * HIDDEN];
__device__ __nv_bfloat16 g_qlo[Q_LEN * HIDDEN];
__device__ __nv_bfloat16 g_khi[KV_LEN * (NKVH * HD)];
__device__ __nv_bfloat16 g_klo[KV_LEN * (NKVH * HD)];
__device__ __nv_bfloat16 g_vthi[NKVH * HD * KV_PAD];
__device__ __nv_bfloat16 g_vtlo[NKVH * HD * KV_PAD];
__device__ __nv_bfloat16 g_attnhi[Q_LEN * HIDDEN];
__device__ __nv_bfloat16 g_attnlo[Q_LEN * HIDDEN];

__device__ __forceinline__ void split2(float x, float y, unsigned& hi, unsigned& lo)
{
    __nv_bfloat16 hx = __float2bfloat16(x), hy = __float2bfloat16(y);
    float lx = x - __bfloat162float(hx), ly = y - __bfloat162float(hy);
    __nv_bfloat16 lxb = __float2bfloat16(lx), lyb = __float2bfloat16(ly);
    hi = (unsigned)__bfloat16_as_ushort(hx) | ((unsigned)__bfloat16_as_ushort(hy) << 16);
    lo = (unsigned)__bfloat16_as_ushort(lxb) | ((unsigned)__bfloat16_as_ushort(lyb) << 16);
}

__device__ __forceinline__ uint32_t smem_u32(const void* p)
{
    uint32_t a;
    asm("{ .reg .u64 t; cvta.to.shared.u64 t, %1; cvt.u32.u64 %0, t; }"
        : "=r"(a) : "l"(p));
    return a;
}
#define CP16(dst, src, n) \
    asm volatile("cp.async.cg.shared.global [%0], [%1], 16, %2;" \
                 :: "r"(dst), "l"(src), "r"(n))
#define CP_COMMIT() asm volatile("cp.async.commit_group;" ::: "memory")
#define CP_WAIT1()  asm volatile("cp.async.wait_group 1;" ::: "memory")

#define MMA_BF16(d, a, b)                                                      \
    asm volatile(                                                              \
        "mma.sync.aligned.m16n8k16.row.col.f32.bf16.bf16.f32 "                 \
        "{%0,%1,%2,%3},{%4,%5,%6,%7},{%8,%9},{%0,%1,%2,%3};"                   \
        : "+f"((d)[0]), "+f"((d)[1]), "+f"((d)[2]), "+f"((d)[3])               \
        : "r"((a)[0]), "r"((a)[1]), "r"((a)[2]), "r"((a)[3]),                  \
          "r"((b)[0]), "r"((b)[1]))

#define LDSM4(r, addr)                                                         \
    asm volatile(                                                              \
        "ldmatrix.sync.aligned.m8n8.x4.shared.b16 {%0,%1,%2,%3}, [%4];"        \
        : "=r"((r)[0]), "=r"((r)[1]), "=r"((r)[2]), "=r"((r)[3])               \
        : "r"(addr))

// ---------------- pipelined bf16x3 GEMM (R10, unchanged) ---------------------
#define GB_BUF   (128 * 128)
#define GB_STAGE (4 * GB_BUF)
#define GB_NST   3
#define GB_SMEM  (GB_NST * GB_STAGE)

__global__ void __launch_bounds__(256, 1) gemm_bf16x3(
    const __nv_bfloat16* __restrict__ Ahi, const __nv_bfloat16* __restrict__ Alo,
    const __nv_bfloat16* __restrict__ Bthi, const __nv_bfloat16* __restrict__ Btlo,
    float* __restrict__ C, int M, int ldc)
{
    extern __shared__ char smg[];
    const uint32_t sb = smem_u32(smg);
    const int tid  = threadIdx.x;
    const int warp = tid >> 5, lane = tid & 31;
    const int g = lane >> 2, tig = lane & 3;
    const int wm = warp & 1, wn = warp >> 1;
    const int row0 = blockIdx.y * 128, col0 = blockIdx.x * 128;
    const int rowbase = wm * 64, colbase = wn * 32;
    const int K = HIDDEN;
    const int nck = K / 64;

    const int a_row_in = lane & 15;
    const int a_ckb    = lane >> 4;
    const int b_row_in = (((lane >> 4) & 1) << 3) + (lane & 7);
    const int b_ckb    = (lane >> 3) & 1;

    float acc[4][4][4];
#pragma unroll
    for (int i = 0; i < 4; i++)
#pragma unroll
        for (int j = 0; j < 4; j++)
#pragma unroll
            for (int t = 0; t < 4; t++) acc[i][j][t] = 0.f;

    auto load_chunk = [&](int ck, int st) {
        const uint32_t stb = sb + st * GB_STAGE;
        const int k0 = ck * 64;
#pragma unroll
        for (int i = 0; i < 4; i++) {
            int idx = tid + i * 256;
            int r = idx >> 3, c = idx & 7;
            uint32_t soff = (uint32_t)(r * 128 + ((c ^ (r & 7)) * 16));
            int gr = row0 + r;
            int ok = (gr < M) ? 16 : 0;
            int grc = (gr < M) ? gr : 0;
            size_t aoff = (size_t)grc * K + k0 + c * 8;
            CP16(stb + 0 * GB_BUF + soff, Ahi + aoff, ok);
            CP16(stb + 1 * GB_BUF + soff, Alo + aoff, ok);
            size_t boff = (size_t)(col0 + r) * K + k0 + c * 8;
            CP16(stb + 2 * GB_BUF + soff, Bthi + boff, 16);
            CP16(stb + 3 * GB_BUF + soff, Btlo + boff, 16);
        }
    };

    load_chunk(0, 0); CP_COMMIT();
    load_chunk(1, 1); CP_COMMIT();

    for (int ck = 0; ck < nck; ck++) {
        const int st = ck % GB_NST;
        CP_WAIT1();
        __syncthreads();
        if (ck + 2 < nck) load_chunk(ck + 2, (ck + 2) % GB_NST);
        CP_COMMIT();

        const uint32_t stb = sb + st * GB_STAGE;

#pragma unroll
        for (int ks = 0; ks < 4; ks++) {
            unsigned ah[4][4], al[4][4], bfr[2][4];
#pragma unroll
            for (int am = 0; am < 4; am++) {
                int row = rowbase + am * 16 + a_row_in;
                int ck4 = (2 * ks + a_ckb) ^ (row & 7);
                uint32_t addr = stb + (uint32_t)(row * 128 + ck4 * 16);
                LDSM4(ah[am], addr);
                LDSM4(al[am], addr + GB_BUF);
            }
            unsigned bh[4][2], bl[4][2];
#pragma unroll
            for (int p = 0; p < 2; p++) {
                int row = colbase + p * 16 + b_row_in;
                int ck4 = (2 * ks + b_ckb) ^ (row & 7);
                uint32_t addr = stb + 2 * GB_BUF + (uint32_t)(row * 128 + ck4 * 16);
                LDSM4(bfr[0], addr);
                LDSM4(bfr[1], addr + GB_BUF);
                bh[2 * p][0] = bfr[0][0]; bh[2 * p][1] = bfr[0][1];
                bh[2 * p + 1][0] = bfr[0][2]; bh[2 * p + 1][1] = bfr[0][3];
                bl[2 * p][0] = bfr[1][0]; bl[2 * p][1] = bfr[1][1];
                bl[2 * p + 1][0] = bfr[1][2]; bl[2 * p + 1][1] = bfr[1][3];
            }
#pragma unroll
            for (int am = 0; am < 4; am++)
#pragma unroll
                for (int an = 0; an < 4; an++) MMA_BF16(acc[am][an], ah[am], bh[an]);
#pragma unroll
            for (int am = 0; am < 4; am++)
#pragma unroll
                for (int an = 0; an < 4; an++) MMA_BF16(acc[am][an], al[am], bh[an]);
#pragma unroll
            for (int am = 0; am < 4; am++)
#pragma unroll
                for (int an = 0; an < 4; an++) MMA_BF16(acc[am][an], ah[am], bl[an]);
        }
        __syncthreads();
    }

#pragma unroll
    for (int am = 0; am < 4; am++) {
#pragma unroll
        for (int an = 0; an < 4; an++) {
            int r = row0 + rowbase + am * 16 + g;
            int c = col0 + colbase + an * 8 + tig * 2;
            if (r < M)
                *(float2*)(C + (size_t)r * ldc + c) =
                    make_float2(acc[am][an][0], acc[am][an][1]);
            if (r + 8 < M)
                *(float2*)(C + (size_t)(r + 8) * ldc + c) =
                    make_float2(acc[am][an][2], acc[am][an][3]);
        }
    }
}

// ---------------- fused activation split ----------------
__global__ void split_acts(const float* __restrict__ hid, const float* __restrict__ cross)
{
    const int nh = Q_LEN * HIDDEN / 4;
    const int nc = KV_LEN * HIDDEN / 4;
    int i = blockIdx.x * blockDim.x + threadIdx.x;
    if (i >= nh + nc) return;
    const float4* src;
    __nv_bfloat16 *hi, *lo;
    int j;
    if (i < nh) { src = (const float4*)hid;   hi = g_hid_hi;   lo = g_hid_lo;   j = i; }
    else        { src = (const float4*)cross; hi = g_cross_hi; lo = g_cross_lo; j = i - nh; }
    float4 v = src[j];
    uint2 uh, ul;
    split2(v.x, v.y, uh.x, ul.x);
    split2(v.z, v.w, uh.y, ul.y);
    ((uint2*)hi)[j] = uh;
    ((uint2*)lo)[j] = ul;
}

// ---------------- fp32 [R][C] -> bf16 hi/lo [C][R] ----------------
__global__ void wtrans_split(const float* __restrict__ w,
                             __nv_bfloat16* __restrict__ hi,
                             __nv_bfloat16* __restrict__ lo, int R, int C)
{
    __shared__ float t[32][33];
    int tx = threadIdx.x, ty = threadIdx.y;
    int r0 = blockIdx.y * 32, c0 = blockIdx.x * 32;
#pragma unroll
    for (int i = 0; i < 4; i++)
        t[ty + 8 * i][tx] = w[(size_t)(r0 + ty + 8 * i) * C + c0 + tx];
    __syncthreads();
#pragma unroll
    for (int i = 0; i < 4; i++) {
        float v = t[tx][ty + 8 * i];
        __nv_bfloat16 hb = __float2bfloat16(v);
        __nv_bfloat16 lb = __float2bfloat16(v - __bfloat162float(hb));
        size_t off = (size_t)(c0 + ty + 8 * i) * R + r0 + tx;
        hi[off] = hb; lo[off] = lb;
    }
}

// ---------------- V transpose+split ----------------
__global__ void vtrans_split(const float* __restrict__ kv)
{
    __shared__ float t[32][33];
    int tx = threadIdx.x, ty = threadIdx.y;
    int kv0 = blockIdx.x * 32, d0 = blockIdx.y * 32, kvh = blockIdx.z;
#pragma unroll
    for (int i = 0; i < 4; i++) {
        int r = kv0 + ty + 8 * i;
        t[ty + 8 * i][tx] = (r < KV_LEN)
            ? kv[(size_t)r * KV_N + NKVH * HD + kvh * HD + d0 + tx] : 0.f;
    }
    __syncthreads();
#pragma unroll
    for (int i = 0; i < 4; i++) {
        float v = t[tx][ty + 8 * i];
        __nv_bfloat16 hb = __float2bfloat16(v);
        __nv_bfloat16 lb = __float2bfloat16(v - __bfloat162float(hb));
        size_t off = (size_t)(kvh * HD + d0 + ty + 8 * i) * KV_PAD + kv0 + tx;
        g_vthi[off] = hb; g_vtlo[off] = lb;
    }
}

// ---------------- RMS norm fp32 -> bf16 hi/lo ----------------
__global__ void rmsnorm_split(const float* __restrict__ x, const float* __restrict__ w,
                              __nv_bfloat16* __restrict__ hi, __nv_bfloat16* __restrict__ lo,
                              int nrows, int nheads, int ld_in, int ld_out)
{
    int gw = (int)((blockIdx.x * blockDim.x + threadIdx.x) >> 5);
    int lane = threadIdx.x & 31;
    if (gw >= nrows * nheads) return;
    int row = gw / nheads, h = gw - row * nheads;
    const float* p = x + (size_t)row * ld_in + h * HD;
    float4 v = *(const float4*)(p + lane * 4);
    float ss = v.x * v.x + v.y * v.y + v.z * v.z + v.w * v.w;
#pragma unroll
    for (int o = 16; o > 0; o >>= 1) ss += __shfl_xor_sync(0xffffffffu, ss, o);
    float s = rsqrtf(ss * (1.f / HD) + 1e-5f);
    float4 wv = *(const float4*)(w + lane * 4);
    v.x *= s * wv.x; v.y *= s * wv.y; v.z *= s * wv.z; v.w *= s * wv.w;
    uint2 uh, ul;
    split2(v.x, v.y, uh.x, ul.x);
    split2(v.z, v.w, uh.y, ul.y);
    size_t off = (size_t)row * ld_out + h * HD + lane * 4;
    *(uint2*)(hi + off) = uh;
    *(uint2*)(lo + off) = ul;
}

// ---------------- flash attention with cp.async K/V pipeline -----------------
// smem bytes: Q 2x34816, K stages 2x(2x17408), V stages 2x(2x18432) = 212992
#define AQST 136            // halves
#define AVST 72             // halves
#define AQH_OFF 0
#define AQL_OFF 34816
#define AK_OFF  69632
#define AK_SS   34816       // per stage (Kh + Kl)
#define AV_OFF  139264
#define AV_SS   36864       // per stage (Vh + Vl)
#define ATTN_SMEM 212992
#define NCHUNK  (KV_PAD / 64)

__global__ void __launch_bounds__(256, 1) attn_mma(const float* __restrict__ mask)
{
    extern __shared__ char sma[];
    const uint32_t sb = smem_u32(sma);
    const int tid = threadIdx.x, warp = tid >> 5, lane = tid & 31;
    const int g = lane >> 2, tig = lane & 3;
    const int h = blockIdx.y, kvh = h >> 2;
    const int q0 = blockIdx.x * 128;
    const int wr = warp * 16;
    const int row0 = q0 + wr + g;

    __nv_bfloat16* Qh = (__nv_bfloat16*)(sma + AQH_OFF);
    __nv_bfloat16* Ql = (__nv_bfloat16*)(sma + AQL_OFF);

    // Q resident (blocking; loaded once)
#pragma unroll
    for (int it = 0; it < 8; it++) {
        int idx = tid + it * 256;
        int r = idx >> 4, c = (idx & 15) * 8;
        size_t off = (size_t)(q0 + r) * HIDDEN + h * HD + c;
        *(uint4*)&Qh[r * AQST + c] = *(const uint4*)(g_qhi + off);
        *(uint4*)&Ql[r * AQST + c] = *(const uint4*)(g_qlo + off);
    }

    auto load_kv = [&](int ck, int st) {
        const int kv0 = ck * 64;
        const uint32_t kb = sb + AK_OFF + st * AK_SS;
        const uint32_t vb = sb + AV_OFF + st * AV_SS;
        // K: 64 rows x 16 chunks of 16B (hi & lo)
#pragma unroll
        for (int i = 0; i < 4; i++) {
            int idx = tid + i * 256;
            int r = idx >> 4, c = idx & 15;
            uint32_t soff = (uint32_t)(r * 272 + c * 16);
            int ok = (kv0 + r < KV_LEN) ? 16 : 0;
            int rc = (kv0 + r < KV_LEN) ? (kv0 + r) : 0;
            size_t goff = (size_t)rc * (NKVH * HD) + kvh * HD + c * 8;
            CP16(kb + soff, g_khi + goff, ok);
            CP16(kb + 17408 + soff, g_klo + goff, ok);
        }
        // V: 128 rows x 8 chunks of 16B (hi & lo); always in-bounds (KV_PAD)
#pragma unroll
        for (int i = 0; i < 4; i++) {
            int idx = tid + i * 256;
            int d = idx >> 3, c = idx & 7;
            uint32_t soff = (uint32_t)(d * 144 + c * 16);
            size_t goff = ((size_t)kvh * HD + d) * KV_PAD + kv0 + c * 8;
            CP16(vb + soff, g_vthi + goff, 16);
            CP16(vb + 18432 + soff, g_vtlo + goff, 16);
        }
    };

    float o[16][4];
#pragma unroll
    for (int n = 0; n < 16; n++)
#pragma unroll
        for (int t = 0; t < 4; t++) o[n][t] = 0.f;
    float m0 = -1e30f, m1 = -1e30f, l0 = 0.f, l1 = 0.f;

    load_kv(0, 0);
    CP_COMMIT();

    for (int ck = 0; ck < NCHUNK; ck++) {
        const int kv0 = ck * 64;
        const int st = ck & 1;
        if (ck + 1 < NCHUNK) load_kv(ck + 1, st ^ 1);
        CP_COMMIT();
        CP_WAIT1();
        __syncthreads();

        const __nv_bfloat16* Kh = (const __nv_bfloat16*)(sma + AK_OFF + st * AK_SS);
        const __nv_bfloat16* Kl = (const __nv_bfloat16*)(sma + AK_OFF + st * AK_SS + 17408);
        const __nv_bfloat16* Vh = (const __nv_bfloat16*)(sma + AV_OFF + st * AV_SS);
        const __nv_bfloat16* Vl = (const __nv_bfloat16*)(sma + AV_OFF + st * AV_SS + 18432);

        float s[8][4];
#pragma unroll
        for (int j = 0; j < 8; j++)
#pragma unroll
            for (int c = 0; c < 4; c++) s[j][c] = 0.f;

#pragma unroll
        for (int kt = 0; kt < 8; kt++) {
            int ab = (wr + g) * AQST + kt * 16 + tig * 2;
            unsigned ah[4], al[4];
            ah[0] = *(const unsigned*)&Qh[ab];
            ah[1] = *(const unsigned*)&Qh[ab + 8 * AQST];
            ah[2] = *(const unsigned*)&Qh[ab + 8];
            ah[3] = *(const unsigned*)&Qh[ab + 8 * AQST + 8];
            al[0] = *(const unsigned*)&Ql[ab];
            al[1] = *(const unsigned*)&Ql[ab + 8 * AQST];
            al[2] = *(const unsigned*)&Ql[ab + 8];
            al[3] = *(const unsigned*)&Ql[ab + 8 * AQST + 8];
#pragma unroll
            for (int j = 0; j < 8; j++) {
                int bb = (8 * j + g) * AQST + kt * 16 + tig * 2;
                unsigned bh[2], bl[2];
                bh[0] = *(const unsigned*)&Kh[bb];
                bh[1] = *(const unsigned*)&Kh[bb + 8];
                bl[0] = *(const unsigned*)&Kl[bb];
                bl[1] = *(const unsigned*)&Kl[bb + 8];
                MMA_BF16(s[j], ah, bh);
                MMA_BF16(s[j], al, bh);
                MMA_BF16(s[j], ah, bl);
            }
        }

        bool partial = (kv0 + 64 > KV_LEN);
        float rmax0 = -1e30f, rmax1 = -1e30f;
        if (!partial) {
#pragma unroll
            for (int j = 0; j < 8; j++) {
                int col = kv0 + 8 * j + tig * 2;
                const float* mp = mask + (size_t)row0 * KV_LEN + col;
                float2 mk0 = *(const float2*)mp;
                float2 mk1 = *(const float2*)(mp + (size_t)8 * KV_LEN);
                s[j][0] = fmaf(s[j][0], ATTN_SCALE, mk0.x);
                s[j][1] = fmaf(s[j][1], ATTN_SCALE, mk0.y);
                s[j][2] = fmaf(s[j][2], ATTN_SCALE, mk1.x);
                s[j][3] = fmaf(s[j][3], ATTN_SCALE, mk1.y);
                rmax0 = fmaxf(rmax0, fmaxf(s[j][0], s[j][1]));
                rmax1 = fmaxf(rmax1, fmaxf(s[j][2], s[j][3]));
            }
        } else {
#pragma unroll
            for (int j = 0; j < 8; j++) {
#pragma unroll
                for (int c = 0; c < 2; c++) {
                    int col = kv0 + 8 * j + tig * 2 + c;
                    if (col < KV_LEN) {
                        s[j][c]     = fmaf(s[j][c], ATTN_SCALE,
                                           mask[(size_t)row0 * KV_LEN + col]);
                        s[j][2 + c] = fmaf(s[j][2 + c], ATTN_SCALE,
                                           mask[(size_t)(row0 + 8) * KV_LEN + col]);
                    } else {
                        s[j][c] = -1e30f;
                        s[j][2 + c] = -1e30f;
                    }
                }
                rmax0 = fmaxf(rmax0, fmaxf(s[j][0], s[j][1]));
                rmax1 = fmaxf(rmax1, fmaxf(s[j][2], s[j][3]));
            }
        }
        rmax0 = fmaxf(rmax0, __shfl_xor_sync(0xffffffffu, rmax0, 1));
        rmax0 = fmaxf(rmax0, __shfl_xor_sync(0xffffffffu, rmax0, 2));
        rmax1 = fmaxf(rmax1, __shfl_xor_sync(0xffffffffu, rmax1, 1));
        rmax1 = fmaxf(rmax1, __shfl_xor_sync(0xffffffffu, rmax1, 2));

        float mn0 = fmaxf(m0, rmax0), mn1 = fmaxf(m1, rmax1);
        float f0 = __expf(m0 - mn0), f1 = __expf(m1 - mn1);
        m0 = mn0; m1 = mn1;

        float sum0 = 0.f, sum1 = 0.f;
#pragma unroll
        for (int j = 0; j < 8; j++) {
            s[j][0] = __expf(s[j][0] - mn0);
            s[j][1] = __expf(s[j][1] - mn0);
            s[j][2] = __expf(s[j][2] - mn1);
            s[j][3] = __expf(s[j][3] - mn1);
            sum0 += s[j][0] + s[j][1];
            sum1 += s[j][2] + s[j][3];
        }
        sum0 += __shfl_xor_sync(0xffffffffu, sum0, 1);
        sum0 += __shfl_xor_sync(0xffffffffu, sum0, 2);
        sum1 += __shfl_xor_sync(0xffffffffu, sum1, 1);
        sum1 += __shfl_xor_sync(0xffffffffu, sum1, 2);
        l0 = l0 * f0 + sum0;
        l1 = l1 * f1 + sum1;

#pragma unroll
        for (int n = 0; n < 16; n++) {
            o[n][0] *= f0; o[n][1] *= f0; o[n][2] *= f1; o[n][3] *= f1;
        }

#pragma unroll
        for (int t = 0; t < 4; t++) {
            unsigned ph[4], pl[4];
            split2(s[2 * t][0],     s[2 * t][1],     ph[0], pl[0]);
            split2(s[2 * t][2],     s[2 * t][3],     ph[1], pl[1]);
            split2(s[2 * t + 1][0], s[2 * t + 1][1], ph[2], pl[2]);
            split2(s[2 * t + 1][2], s[2 * t + 1][3], ph[3], pl[3]);
#pragma unroll
            for (int n = 0; n < 16; n++) {
                int vb = (8 * n + g) * AVST + t * 16 + tig * 2;
                unsigned bh[2], bl[2];
                bh[0] = *(const unsigned*)&Vh[vb];
                bh[1] = *(const unsigned*)&Vh[vb + 8];
                bl[0] = *(const unsigned*)&Vl[vb];
                bl[1] = *(const unsigned*)&Vl[vb + 8];
                MMA_BF16(o[n], ph, bh);
                MMA_BF16(o[n], pl, bh);
                MMA_BF16(o[n], ph, bl);
            }
        }
        __syncthreads();
    }

    float il0 = 1.f / l0, il1 = 1.f / l1;
#pragma unroll
    for (int n = 0; n < 16; n++) {
        unsigned h01, lo01, h23, lo23;
        split2(o[n][0] * il0, o[n][1] * il0, h01, lo01);
        split2(o[n][2] * il1, o[n][3] * il1, h23, lo23);
        size_t base = (size_t)row0 * HIDDEN + h * HD + 8 * n + tig * 2;
        *(unsigned*)(g_attnhi + base) = h01;
        *(unsigned*)(g_attnlo + base) = lo01;
        *(unsigned*)(g_attnhi + base + (size_t)8 * HIDDEN) = h23;
        *(unsigned*)(g_attnlo + base + (size_t)8 * HIDDEN) = lo23;
    }
}

// ---------------------------------------------------------------------------
extern "C" void kernel_launch(void* const* d_in, const int* in_sizes, int n_in,
                              void* d_out, int out_size)
{
    const float* hidden = (const float*)d_in[0];
    const float* cross  = (const float*)d_in[1];
    const float* mask   = (const float*)d_in[2];
    const float* w_qkv  = (const float*)d_in[3];
    const float* w_o    = (const float*)d_in[4];
    const float* q_norm = (const float*)d_in[5];
    const float* k_norm = (const float*)d_in[6];
    float* out = (float*)d_out;
    (void)in_sizes; (void)n_in; (void)out_size;

    float *pq, *pkv;
    cudaGetSymbolAddress((void**)&pq,  g_q);
    cudaGetSymbolAddress((void**)&pkv, g_kv);
    __nv_bfloat16 *hid_hi, *hid_lo, *cross_hi, *cross_lo;
    __nv_bfloat16 *wqkvT_hi, *wqkvT_lo, *woT_hi, *woT_lo;
    __nv_bfloat16 *qhi, *qlo, *khi, *klo, *attnhi, *attnlo;
    cudaGetSymbolAddress((void**)&hid_hi,   g_hid_hi);
    cudaGetSymbolAddress((void**)&hid_lo,   g_hid_lo);
    cudaGetSymbolAddress((void**)&cross_hi, g_cross_hi);
    cudaGetSymbolAddress((void**)&cross_lo, g_cross_lo);
    cudaGetSymbolAddress((void**)&wqkvT_hi, g_wqkvT_hi);
    cudaGetSymbolAddress((void**)&wqkvT_lo, g_wqkvT_lo);
    cudaGetSymbolAddress((void**)&woT_hi,   g_woT_hi);
    cudaGetSymbolAddress((void**)&woT_lo,   g_woT_lo);
    cudaGetSymbolAddress((void**)&qhi,      g_qhi);
    cudaGetSymbolAddress((void**)&qlo,      g_qlo);
    cudaGetSymbolAddress((void**)&khi,      g_khi);
    cudaGetSymbolAddress((void**)&klo,      g_klo);
    cudaGetSymbolAddress((void**)&attnhi,   g_attnhi);
    cudaGetSymbolAddress((void**)&attnlo,   g_attnlo);

    // 1) fused activation split
    {
        int n4 = (Q_LEN + KV_LEN) * HIDDEN / 4;
        split_acts<<<(n4 + 255) / 256, 256>>>(hidden, cross);
    }
    // 2,3) weight transpose + split
    wtrans_split<<<dim3(QKV_LDB / 32, HIDDEN / 32), dim3(32, 8)>>>(
        w_qkv, wqkvT_hi, wqkvT_lo, HIDDEN, QKV_LDB);
    wtrans_split<<<dim3(HIDDEN / 32, HIDDEN / 32), dim3(32, 8)>>>(
        w_o, woT_hi, woT_lo, HIDDEN, HIDDEN);

    cudaFuncSetAttribute(gemm_bf16x3, cudaFuncAttributeMaxDynamicSharedMemorySize,
                         GB_SMEM);

    // 4) KV projection: M=6404, N=2048
    gemm_bf16x3<<<dim3(KV_N / 128, (KV_LEN + 127) / 128), 256, GB_SMEM>>>(
        cross_hi, cross_lo,
        wqkvT_hi + (size_t)(NH * HD) * HIDDEN, wqkvT_lo + (size_t)(NH * HD) * HIDDEN,
        pkv, KV_LEN, KV_N);
    // 5) Q projection: M=1024, N=4096
    gemm_bf16x3<<<dim3(HIDDEN / 128, Q_LEN / 128), 256, GB_SMEM>>>(
        hid_hi, hid_lo, wqkvT_hi, wqkvT_lo, pq, Q_LEN, HIDDEN);

    // 6,7) RMS norms -> bf16 hi/lo
    {
        int nwarps = Q_LEN * NH;
        rmsnorm_split<<<(nwarps * 32 + 255) / 256, 256>>>(
            pq, q_norm, qhi, qlo, Q_LEN, NH, HIDDEN, HIDDEN);
        nwarps = KV_LEN * NKVH;
        rmsnorm_split<<<(nwarps * 32 + 255) / 256, 256>>>(
            pkv, k_norm, khi, klo, KV_LEN, NKVH, KV_N, NKVH * HD);
    }
    // 8) V transpose + split
    vtrans_split<<<dim3(KV_PAD / 32, HD / 32, NKVH), dim3(32, 8)>>>(pkv);

    // 9) attention (cp.async pipelined K/V)
    cudaFuncSetAttribute(attn_mma, cudaFuncAttributeMaxDynamicSharedMemorySize,
                         ATTN_SMEM);
    attn_mma<<<dim3(Q_LEN / 128, NH), 256, ATTN_SMEM>>>(mask);

    // 10) O projection: M=1024, N=4096
    gemm_bf16x3<<<dim3(HIDDEN / 128, Q_LEN / 128), 256, GB_SMEM>>>(
        attnhi, attnlo, woT_hi, woT_lo, out, Q_LEN, HIDDEN);
}

// round 13
// speedup vs baseline: 2.7243x; 1.0449x over previous
#include <cuda_runtime.h>
#include <cuda_bf16.h>
#include <stdint.h>
#include <math.h>

#define Q_LEN   1024
#define KV_LEN  6404
#define KV_PAD  6464
#define HIDDEN  4096
#define NH      32
#define NKVH    8
#define HD      128
#define QKV_LDB 6144
#define KV_N    2048
#define ATTN_SCALE 0.08838834764831845f

// ---------------- scratch ----------------
__device__ float g_q[Q_LEN * HIDDEN];
__device__ float g_kv[KV_LEN * KV_N];

__device__ __nv_bfloat16 g_hid_hi[Q_LEN * HIDDEN];
__device__ __nv_bfloat16 g_hid_lo[Q_LEN * HIDDEN];
__device__ __nv_bfloat16 g_cross_hi[KV_LEN * HIDDEN];
__device__ __nv_bfloat16 g_cross_lo[KV_LEN * HIDDEN];
__device__ __nv_bfloat16 g_wqkvT_hi[QKV_LDB * HIDDEN];
__device__ __nv_bfloat16 g_wqkvT_lo[QKV_LDB * HIDDEN];
__device__ __nv_bfloat16 g_woT_hi[HIDDEN * HIDDEN];
__device__ __nv_bfloat16 g_woT_lo[HIDDEN * HIDDEN];
__device__ __nv_bfloat16 g_qhi[Q_LEN * HIDDEN];
__device__ __nv_bfloat16 g_qlo[Q_LEN * HIDDEN];
__device__ __nv_bfloat16 g_khi[KV_LEN * (NKVH * HD)];
__device__ __nv_bfloat16 g_klo[KV_LEN * (NKVH * HD)];
__device__ __nv_bfloat16 g_vthi[NKVH * HD * KV_PAD];
__device__ __nv_bfloat16 g_vtlo[NKVH * HD * KV_PAD];
__device__ __nv_bfloat16 g_attnhi[Q_LEN * HIDDEN];
__device__ __nv_bfloat16 g_attnlo[Q_LEN * HIDDEN];

__device__ __forceinline__ void split2(float x, float y, unsigned& hi, unsigned& lo)
{
    __nv_bfloat16 hx = __float2bfloat16(x), hy = __float2bfloat16(y);
    float lx = x - __bfloat162float(hx), ly = y - __bfloat162float(hy);
    __nv_bfloat16 lxb = __float2bfloat16(lx), lyb = __float2bfloat16(ly);
    hi = (unsigned)__bfloat16_as_ushort(hx) | ((unsigned)__bfloat16_as_ushort(hy) << 16);
    lo = (unsigned)__bfloat16_as_ushort(lxb) | ((unsigned)__bfloat16_as_ushort(lyb) << 16);
}

__device__ __forceinline__ uint32_t smem_u32(const void* p)
{
    uint32_t a;
    asm("{ .reg .u64 t; cvta.to.shared.u64 t, %1; cvt.u32.u64 %0, t; }"
        : "=r"(a) : "l"(p));
    return a;
}
#define CP16(dst, src, n) \
    asm volatile("cp.async.cg.shared.global [%0], [%1], 16, %2;" \
                 :: "r"(dst), "l"(src), "r"(n))
#define CP_COMMIT() asm volatile("cp.async.commit_group;" ::: "memory")
#define CP_WAIT1()  asm volatile("cp.async.wait_group 1;" ::: "memory")

#define MMA_BF16(d, a, b)                                                      \
    asm volatile(                                                              \
        "mma.sync.aligned.m16n8k16.row.col.f32.bf16.bf16.f32 "                 \
        "{%0,%1,%2,%3},{%4,%5,%6,%7},{%8,%9},{%0,%1,%2,%3};"                   \
        : "+f"((d)[0]), "+f"((d)[1]), "+f"((d)[2]), "+f"((d)[3])               \
        : "r"((a)[0]), "r"((a)[1]), "r"((a)[2]), "r"((a)[3]),                  \
          "r"((b)[0]), "r"((b)[1]))

#define LDSM4(r, addr)                                                         \
    asm volatile(                                                              \
        "ldmatrix.sync.aligned.m8n8.x4.shared.b16 {%0,%1,%2,%3}, [%4];"        \
        : "=r"((r)[0]), "=r"((r)[1]), "=r"((r)[2]), "=r"((r)[3])               \
        : "r"(addr))

// ---------------- bf16x3 GEMM, block 128x256, warp tile 64x64 ----------------
// A: 128 rows x 128B (hi+lo = 32KB), B: 256 rows x 128B (hi+lo = 64KB);
// stage = 96KB, 2-stage ring = 192KB. 8 warps (2m x 4n).
#define GA_BUF   (128 * 128)
#define GBB_BUF  (256 * 128)
#define GS_AH    0
#define GS_AL    GA_BUF
#define GS_BH    (2 * GA_BUF)
#define GS_BL    (2 * GA_BUF + GBB_BUF)
#define GB_STAGE (2 * GA_BUF + 2 * GBB_BUF)
#define GB_SMEM  (2 * GB_STAGE)

__global__ void __launch_bounds__(256, 1) gemm_bf16x3(
    const __nv_bfloat16* __restrict__ Ahi, const __nv_bfloat16* __restrict__ Alo,
    const __nv_bfloat16* __restrict__ Bthi, const __nv_bfloat16* __restrict__ Btlo,
    float* __restrict__ C, int M, int ldc)
{
    extern __shared__ char smg[];
    const uint32_t sb = smem_u32(smg);
    const int tid  = threadIdx.x;
    const int warp = tid >> 5, lane = tid & 31;
    const int g = lane >> 2, tig = lane & 3;
    const int wm = warp & 1, wn = warp >> 1;
    const int row0 = blockIdx.y * 128, col0 = blockIdx.x * 256;
    const int rowbase = wm * 64, colbase = wn * 64;
    const int K = HIDDEN;
    const int nck = K / 64;

    const int a_row_in = lane & 15;
    const int a_ckb    = lane >> 4;
    const int b_row_in = (((lane >> 4) & 1) << 3) + (lane & 7);
    const int b_ckb    = (lane >> 3) & 1;

    float acc[4][8][4];
#pragma unroll
    for (int i = 0; i < 4; i++)
#pragma unroll
        for (int j = 0; j < 8; j++)
#pragma unroll
            for (int t = 0; t < 4; t++) acc[i][j][t] = 0.f;

    auto load_chunk = [&](int ck, int st) {
        const uint32_t stb = sb + st * GB_STAGE;
        const int k0 = ck * 64;
        // A hi/lo: 128 rows x 8 x 16B = 1024 per buf
#pragma unroll
        for (int i = 0; i < 4; i++) {
            int idx = tid + i * 256;
            int r = idx >> 3, c = idx & 7;
            uint32_t soff = (uint32_t)(r * 128 + ((c ^ (r & 7)) * 16));
            int gr = row0 + r;
            int ok = (gr < M) ? 16 : 0;
            int grc = (gr < M) ? gr : 0;
            size_t aoff = (size_t)grc * K + k0 + c * 8;
            CP16(stb + GS_AH + soff, Ahi + aoff, ok);
            CP16(stb + GS_AL + soff, Alo + aoff, ok);
        }
        // B hi/lo: 256 rows x 8 x 16B = 2048 per buf
#pragma unroll
        for (int i = 0; i < 8; i++) {
            int idx = tid + i * 256;
            int r = idx >> 3, c = idx & 7;
            uint32_t soff = (uint32_t)(r * 128 + ((c ^ (r & 7)) * 16));
            size_t boff = (size_t)(col0 + r) * K + k0 + c * 8;
            CP16(stb + GS_BH + soff, Bthi + boff, 16);
            CP16(stb + GS_BL + soff, Btlo + boff, 16);
        }
    };

    load_chunk(0, 0);
    CP_COMMIT();

    for (int ck = 0; ck < nck; ck++) {
        const int st = ck & 1;
        if (ck + 1 < nck) load_chunk(ck + 1, st ^ 1);
        CP_COMMIT();
        CP_WAIT1();
        __syncthreads();

        const uint32_t stb = sb + st * GB_STAGE;

#pragma unroll
        for (int ks = 0; ks < 4; ks++) {
            unsigned ah[4][4], al[4][4], bb[8][2], bfr[4];
#pragma unroll
            for (int am = 0; am < 4; am++) {
                int row = rowbase + am * 16 + a_row_in;
                int ck4 = (2 * ks + a_ckb) ^ (row & 7);
                uint32_t addr = stb + (uint32_t)(row * 128 + ck4 * 16);
                LDSM4(ah[am], addr);
                LDSM4(al[am], addr + GA_BUF);
            }
            // B hi fragments (4 pairs -> 8 n-tiles)
#pragma unroll
            for (int p = 0; p < 4; p++) {
                int row = colbase + p * 16 + b_row_in;
                int ck4 = (2 * ks + b_ckb) ^ (row & 7);
                uint32_t addr = stb + GS_BH + (uint32_t)(row * 128 + ck4 * 16);
                LDSM4(bfr, addr);
                bb[2 * p][0] = bfr[0]; bb[2 * p][1] = bfr[1];
                bb[2 * p + 1][0] = bfr[2]; bb[2 * p + 1][1] = bfr[3];
            }
#pragma unroll
            for (int am = 0; am < 4; am++)
#pragma unroll
                for (int an = 0; an < 8; an++) MMA_BF16(acc[am][an], ah[am], bb[an]);
#pragma unroll
            for (int am = 0; am < 4; am++)
#pragma unroll
                for (int an = 0; an < 8; an++) MMA_BF16(acc[am][an], al[am], bb[an]);
            // B lo fragments overwrite bb
#pragma unroll
            for (int p = 0; p < 4; p++) {
                int row = colbase + p * 16 + b_row_in;
                int ck4 = (2 * ks + b_ckb) ^ (row & 7);
                uint32_t addr = stb + GS_BL + (uint32_t)(row * 128 + ck4 * 16);
                LDSM4(bfr, addr);
                bb[2 * p][0] = bfr[0]; bb[2 * p][1] = bfr[1];
                bb[2 * p + 1][0] = bfr[2]; bb[2 * p + 1][1] = bfr[3];
            }
#pragma unroll
            for (int am = 0; am < 4; am++)
#pragma unroll
                for (int an = 0; an < 8; an++) MMA_BF16(acc[am][an], ah[am], bb[an]);
        }
        __syncthreads();
    }

    // ---- epilogue ----
#pragma unroll
    for (int am = 0; am < 4; am++) {
#pragma unroll
        for (int an = 0; an < 8; an++) {
            int r = row0 + rowbase + am * 16 + g;
            int c = col0 + colbase + an * 8 + tig * 2;
            if (r < M)
                *(float2*)(C + (size_t)r * ldc + c) =
                    make_float2(acc[am][an][0], acc[am][an][1]);
            if (r + 8 < M)
                *(float2*)(C + (size_t)(r + 8) * ldc + c) =
                    make_float2(acc[am][an][2], acc[am][an][3]);
        }
    }
}

// ---------------- fused activation split ----------------
__global__ void split_acts(const float* __restrict__ hid, const float* __restrict__ cross)
{
    const int nh = Q_LEN * HIDDEN / 4;
    const int nc = KV_LEN * HIDDEN / 4;
    int i = blockIdx.x * blockDim.x + threadIdx.x;
    if (i >= nh + nc) return;
    const float4* src;
    __nv_bfloat16 *hi, *lo;
    int j;
    if (i < nh) { src = (const float4*)hid;   hi = g_hid_hi;   lo = g_hid_lo;   j = i; }
    else        { src = (const float4*)cross; hi = g_cross_hi; lo = g_cross_lo; j = i - nh; }
    float4 v = src[j];
    uint2 uh, ul;
    split2(v.x, v.y, uh.x, ul.x);
    split2(v.z, v.w, uh.y, ul.y);
    ((uint2*)hi)[j] = uh;
    ((uint2*)lo)[j] = ul;
}

// ---------------- fp32 [R][C] -> bf16 hi/lo [C][R] ----------------
__global__ void wtrans_split(const float* __restrict__ w,
                             __nv_bfloat16* __restrict__ hi,
                             __nv_bfloat16* __restrict__ lo, int R, int C)
{
    __shared__ float t[32][33];
    int tx = threadIdx.x, ty = threadIdx.y;
    int r0 = blockIdx.y * 32, c0 = blockIdx.x * 32;
#pragma unroll
    for (int i = 0; i < 4; i++)
        t[ty + 8 * i][tx] = w[(size_t)(r0 + ty + 8 * i) * C + c0 + tx];
    __syncthreads();
#pragma unroll
    for (int i = 0; i < 4; i++) {
        float v = t[tx][ty + 8 * i];
        __nv_bfloat16 hb = __float2bfloat16(v);
        __nv_bfloat16 lb = __float2bfloat16(v - __bfloat162float(hb));
        size_t off = (size_t)(c0 + ty + 8 * i) * R + r0 + tx;
        hi[off] = hb; lo[off] = lb;
    }
}

// ---------------- V transpose+split ----------------
__global__ void vtrans_split(const float* __restrict__ kv)
{
    __shared__ float t[32][33];
    int tx = threadIdx.x, ty = threadIdx.y;
    int kv0 = blockIdx.x * 32, d0 = blockIdx.y * 32, kvh = blockIdx.z;
#pragma unroll
    for (int i = 0; i < 4; i++) {
        int r = kv0 + ty + 8 * i;
        t[ty + 8 * i][tx] = (r < KV_LEN)
            ? kv[(size_t)r * KV_N + NKVH * HD + kvh * HD + d0 + tx] : 0.f;
    }
    __syncthreads();
#pragma unroll
    for (int i = 0; i < 4; i++) {
        float v = t[tx][ty + 8 * i];
        __nv_bfloat16 hb = __float2bfloat16(v);
        __nv_bfloat16 lb = __float2bfloat16(v - __bfloat162float(hb));
        size_t off = (size_t)(kvh * HD + d0 + ty + 8 * i) * KV_PAD + kv0 + tx;
        g_vthi[off] = hb; g_vtlo[off] = lb;
    }
}

// ---------------- RMS norm fp32 -> bf16 hi/lo ----------------
__global__ void rmsnorm_split(const float* __restrict__ x, const float* __restrict__ w,
                              __nv_bfloat16* __restrict__ hi, __nv_bfloat16* __restrict__ lo,
                              int nrows, int nheads, int ld_in, int ld_out)
{
    int gw = (int)((blockIdx.x * blockDim.x + threadIdx.x) >> 5);
    int lane = threadIdx.x & 31;
    if (gw >= nrows * nheads) return;
    int row = gw / nheads, h = gw - row * nheads;
    const float* p = x + (size_t)row * ld_in + h * HD;
    float4 v = *(const float4*)(p + lane * 4);
    float ss = v.x * v.x + v.y * v.y + v.z * v.z + v.w * v.w;
#pragma unroll
    for (int o = 16; o > 0; o >>= 1) ss += __shfl_xor_sync(0xffffffffu, ss, o);
    float s = rsqrtf(ss * (1.f / HD) + 1e-5f);
    float4 wv = *(const float4*)(w + lane * 4);
    v.x *= s * wv.x; v.y *= s * wv.y; v.z *= s * wv.z; v.w *= s * wv.w;
    uint2 uh, ul;
    split2(v.x, v.y, uh.x, ul.x);
    split2(v.z, v.w, uh.y, ul.y);
    size_t off = (size_t)row * ld_out + h * HD + lane * 4;
    *(uint2*)(hi + off) = uh;
    *(uint2*)(lo + off) = ul;
}

// ---------------- flash attention with cp.async K/V pipeline (R11) -----------
#define AQST 136
#define AVST 72
#define AQH_OFF 0
#define AQL_OFF 34816
#define AK_OFF  69632
#define AK_SS   34816
#define AV_OFF  139264
#define AV_SS   36864
#define ATTN_SMEM 212992
#define NCHUNK  (KV_PAD / 64)

__global__ void __launch_bounds__(256, 1) attn_mma(const float* __restrict__ mask)
{
    extern __shared__ char sma[];
    const uint32_t sb = smem_u32(sma);
    const int tid = threadIdx.x, warp = tid >> 5, lane = tid & 31;
    const int g = lane >> 2, tig = lane & 3;
    const int h = blockIdx.y, kvh = h >> 2;
    const int q0 = blockIdx.x * 128;
    const int wr = warp * 16;
    const int row0 = q0 + wr + g;

    __nv_bfloat16* Qh = (__nv_bfloat16*)(sma + AQH_OFF);
    __nv_bfloat16* Ql = (__nv_bfloat16*)(sma + AQL_OFF);

#pragma unroll
    for (int it = 0; it < 8; it++) {
        int idx = tid + it * 256;
        int r = idx >> 4, c = (idx & 15) * 8;
        size_t off = (size_t)(q0 + r) * HIDDEN + h * HD + c;
        *(uint4*)&Qh[r * AQST + c] = *(const uint4*)(g_qhi + off);
        *(uint4*)&Ql[r * AQST + c] = *(const uint4*)(g_qlo + off);
    }

    auto load_kv = [&](int ck, int st) {
        const int kv0 = ck * 64;
        const uint32_t kb = sb + AK_OFF + st * AK_SS;
        const uint32_t vb = sb + AV_OFF + st * AV_SS;
#pragma unroll
        for (int i = 0; i < 4; i++) {
            int idx = tid + i * 256;
            int r = idx >> 4, c = idx & 15;
            uint32_t soff = (uint32_t)(r * 272 + c * 16);
            int ok = (kv0 + r < KV_LEN) ? 16 : 0;
            int rc = (kv0 + r < KV_LEN) ? (kv0 + r) : 0;
            size_t goff = (size_t)rc * (NKVH * HD) + kvh * HD + c * 8;
            CP16(kb + soff, g_khi + goff, ok);
            CP16(kb + 17408 + soff, g_klo + goff, ok);
        }
#pragma unroll
        for (int i = 0; i < 4; i++) {
            int idx = tid + i * 256;
            int d = idx >> 3, c = idx & 7;
            uint32_t soff = (uint32_t)(d * 144 + c * 16);
            size_t goff = ((size_t)kvh * HD + d) * KV_PAD + kv0 + c * 8;
            CP16(vb + soff, g_vthi + goff, 16);
            CP16(vb + 18432 + soff, g_vtlo + goff, 16);
        }
    };

    float o[16][4];
#pragma unroll
    for (int n = 0; n < 16; n++)
#pragma unroll
        for (int t = 0; t < 4; t++) o[n][t] = 0.f;
    float m0 = -1e30f, m1 = -1e30f, l0 = 0.f, l1 = 0.f;

    load_kv(0, 0);
    CP_COMMIT();

    for (int ck = 0; ck < NCHUNK; ck++) {
        const int kv0 = ck * 64;
        const int st = ck & 1;
        if (ck + 1 < NCHUNK) load_kv(ck + 1, st ^ 1);
        CP_COMMIT();
        CP_WAIT1();
        __syncthreads();

        const __nv_bfloat16* Kh = (const __nv_bfloat16*)(sma + AK_OFF + st * AK_SS);
        const __nv_bfloat16* Kl = (const __nv_bfloat16*)(sma + AK_OFF + st * AK_SS + 17408);
        const __nv_bfloat16* Vh = (const __nv_bfloat16*)(sma + AV_OFF + st * AV_SS);
        const __nv_bfloat16* Vl = (const __nv_bfloat16*)(sma + AV_OFF + st * AV_SS + 18432);

        float s[8][4];
#pragma unroll
        for (int j = 0; j < 8; j++)
#pragma unroll
            for (int c = 0; c < 4; c++) s[j][c] = 0.f;

#pragma unroll
        for (int kt = 0; kt < 8; kt++) {
            int ab = (wr + g) * AQST + kt * 16 + tig * 2;
            unsigned ah[4], al[4];
            ah[0] = *(const unsigned*)&Qh[ab];
            ah[1] = *(const unsigned*)&Qh[ab + 8 * AQST];
            ah[2] = *(const unsigned*)&Qh[ab + 8];
            ah[3] = *(const unsigned*)&Qh[ab + 8 * AQST + 8];
            al[0] = *(const unsigned*)&Ql[ab];
            al[1] = *(const unsigned*)&Ql[ab + 8 * AQST];
            al[2] = *(const unsigned*)&Ql[ab + 8];
            al[3] = *(const unsigned*)&Ql[ab + 8 * AQST + 8];
#pragma unroll
            for (int j = 0; j < 8; j++) {
                int bb = (8 * j + g) * AQST + kt * 16 + tig * 2;
                unsigned bh[2], bl[2];
                bh[0] = *(const unsigned*)&Kh[bb];
                bh[1] = *(const unsigned*)&Kh[bb + 8];
                bl[0] = *(const unsigned*)&Kl[bb];
                bl[1] = *(const unsigned*)&Kl[bb + 8];
                MMA_BF16(s[j], ah, bh);
                MMA_BF16(s[j], al, bh);
                MMA_BF16(s[j], ah, bl);
            }
        }

        bool partial = (kv0 + 64 > KV_LEN);
        float rmax0 = -1e30f, rmax1 = -1e30f;
        if (!partial) {
#pragma unroll
            for (int j = 0; j < 8; j++) {
                int col = kv0 + 8 * j + tig * 2;
                const float* mp = mask + (size_t)row0 * KV_LEN + col;
                float2 mk0 = *(const float2*)mp;
                float2 mk1 = *(const float2*)(mp + (size_t)8 * KV_LEN);
                s[j][0] = fmaf(s[j][0], ATTN_SCALE, mk0.x);
                s[j][1] = fmaf(s[j][1], ATTN_SCALE, mk0.y);
                s[j][2] = fmaf(s[j][2], ATTN_SCALE, mk1.x);
                s[j][3] = fmaf(s[j][3], ATTN_SCALE, mk1.y);
                rmax0 = fmaxf(rmax0, fmaxf(s[j][0], s[j][1]));
                rmax1 = fmaxf(rmax1, fmaxf(s[j][2], s[j][3]));
            }
        } else {
#pragma unroll
            for (int j = 0; j < 8; j++) {
#pragma unroll
                for (int c = 0; c < 2; c++) {
                    int col = kv0 + 8 * j + tig * 2 + c;
                    if (col < KV_LEN) {
                        s[j][c]     = fmaf(s[j][c], ATTN_SCALE,
                                           mask[(size_t)row0 * KV_LEN + col]);
                        s[j][2 + c] = fmaf(s[j][2 + c], ATTN_SCALE,
                                           mask[(size_t)(row0 + 8) * KV_LEN + col]);
                    } else {
                        s[j][c] = -1e30f;
                        s[j][2 + c] = -1e30f;
                    }
                }
                rmax0 = fmaxf(rmax0, fmaxf(s[j][0], s[j][1]));
                rmax1 = fmaxf(rmax1, fmaxf(s[j][2], s[j][3]));
            }
        }
        rmax0 = fmaxf(rmax0, __shfl_xor_sync(0xffffffffu, rmax0, 1));
        rmax0 = fmaxf(rmax0, __shfl_xor_sync(0xffffffffu, rmax0, 2));
        rmax1 = fmaxf(rmax1, __shfl_xor_sync(0xffffffffu, rmax1, 1));
        rmax1 = fmaxf(rmax1, __shfl_xor_sync(0xffffffffu, rmax1, 2));

        float mn0 = fmaxf(m0, rmax0), mn1 = fmaxf(m1, rmax1);
        float f0 = __expf(m0 - mn0), f1 = __expf(m1 - mn1);
        m0 = mn0; m1 = mn1;

        float sum0 = 0.f, sum1 = 0.f;
#pragma unroll
        for (int j = 0; j < 8; j++) {
            s[j][0] = __expf(s[j][0] - mn0);
            s[j][1] = __expf(s[j][1] - mn0);
            s[j][2] = __expf(s[j][2] - mn1);
            s[j][3] = __expf(s[j][3] - mn1);
            sum0 += s[j][0] + s[j][1];
            sum1 += s[j][2] + s[j][3];
        }
        sum0 += __shfl_xor_sync(0xffffffffu, sum0, 1);
        sum0 += __shfl_xor_sync(0xffffffffu, sum0, 2);
        sum1 += __shfl_xor_sync(0xffffffffu, sum1, 1);
        sum1 += __shfl_xor_sync(0xffffffffu, sum1, 2);
        l0 = l0 * f0 + sum0;
        l1 = l1 * f1 + sum1;

#pragma unroll
        for (int n = 0; n < 16; n++) {
            o[n][0] *= f0; o[n][1] *= f0; o[n][2] *= f1; o[n][3] *= f1;
        }

#pragma unroll
        for (int t = 0; t < 4; t++) {
            unsigned ph[4], pl[4];
            split2(s[2 * t][0],     s[2 * t][1],     ph[0], pl[0]);
            split2(s[2 * t][2],     s[2 * t][3],     ph[1], pl[1]);
            split2(s[2 * t + 1][0], s[2 * t + 1][1], ph[2], pl[2]);
            split2(s[2 * t + 1][2], s[2 * t + 1][3], ph[3], pl[3]);
#pragma unroll
            for (int n = 0; n < 16; n++) {
                int vb = (8 * n + g) * AVST + t * 16 + tig * 2;
                unsigned bh[2], bl[2];
                bh[0] = *(const unsigned*)&Vh[vb];
                bh[1] = *(const unsigned*)&Vh[vb + 8];
                bl[0] = *(const unsigned*)&Vl[vb];
                bl[1] = *(const unsigned*)&Vl[vb + 8];
                MMA_BF16(o[n], ph, bh);
                MMA_BF16(o[n], pl, bh);
                MMA_BF16(o[n], ph, bl);
            }
        }
        __syncthreads();
    }

    float il0 = 1.f / l0, il1 = 1.f / l1;
#pragma unroll
    for (int n = 0; n < 16; n++) {
        unsigned h01, lo01, h23, lo23;
        split2(o[n][0] * il0, o[n][1] * il0, h01, lo01);
        split2(o[n][2] * il1, o[n][3] * il1, h23, lo23);
        size_t base = (size_t)row0 * HIDDEN + h * HD + 8 * n + tig * 2;
        *(unsigned*)(g_attnhi + base) = h01;
        *(unsigned*)(g_attnlo + base) = lo01;
        *(unsigned*)(g_attnhi + base + (size_t)8 * HIDDEN) = h23;
        *(unsigned*)(g_attnlo + base + (size_t)8 * HIDDEN) = lo23;
    }
}

// ---------------------------------------------------------------------------
extern "C" void kernel_launch(void* const* d_in, const int* in_sizes, int n_in,
                              void* d_out, int out_size)
{
    const float* hidden = (const float*)d_in[0];
    const float* cross  = (const float*)d_in[1];
    const float* mask   = (const float*)d_in[2];
    const float* w_qkv  = (const float*)d_in[3];
    const float* w_o    = (const float*)d_in[4];
    const float* q_norm = (const float*)d_in[5];
    const float* k_norm = (const float*)d_in[6];
    float* out = (float*)d_out;
    (void)in_sizes; (void)n_in; (void)out_size;

    float *pq, *pkv;
    cudaGetSymbolAddress((void**)&pq,  g_q);
    cudaGetSymbolAddress((void**)&pkv, g_kv);
    __nv_bfloat16 *hid_hi, *hid_lo, *cross_hi, *cross_lo;
    __nv_bfloat16 *wqkvT_hi, *wqkvT_lo, *woT_hi, *woT_lo;
    __nv_bfloat16 *qhi, *qlo, *khi, *klo, *attnhi, *attnlo;
    cudaGetSymbolAddress((void**)&hid_hi,   g_hid_hi);
    cudaGetSymbolAddress((void**)&hid_lo,   g_hid_lo);
    cudaGetSymbolAddress((void**)&cross_hi, g_cross_hi);
    cudaGetSymbolAddress((void**)&cross_lo, g_cross_lo);
    cudaGetSymbolAddress((void**)&wqkvT_hi, g_wqkvT_hi);
    cudaGetSymbolAddress((void**)&wqkvT_lo, g_wqkvT_lo);
    cudaGetSymbolAddress((void**)&woT_hi,   g_woT_hi);
    cudaGetSymbolAddress((void**)&woT_lo,   g_woT_lo);
    cudaGetSymbolAddress((void**)&qhi,      g_qhi);
    cudaGetSymbolAddress((void**)&qlo,      g_qlo);
    cudaGetSymbolAddress((void**)&khi,      g_khi);
    cudaGetSymbolAddress((void**)&klo,      g_klo);
    cudaGetSymbolAddress((void**)&attnhi,   g_attnhi);
    cudaGetSymbolAddress((void**)&attnlo,   g_attnlo);

    // 1) fused activation split
    {
        int n4 = (Q_LEN + KV_LEN) * HIDDEN / 4;
        split_acts<<<(n4 + 255) / 256, 256>>>(hidden, cross);
    }
    // 2,3) weight transpose + split
    wtrans_split<<<dim3(QKV_LDB / 32, HIDDEN / 32), dim3(32, 8)>>>(
        w_qkv, wqkvT_hi, wqkvT_lo, HIDDEN, QKV_LDB);
    wtrans_split<<<dim3(HIDDEN / 32, HIDDEN / 32), dim3(32, 8)>>>(
        w_o, woT_hi, woT_lo, HIDDEN, HIDDEN);

    cudaFuncSetAttribute(gemm_bf16x3, cudaFuncAttributeMaxDynamicSharedMemorySize,
                         GB_SMEM);

    // 4) KV projection: M=6404, N=2048 (grid 8 x 51)
    gemm_bf16x3<<<dim3(KV_N / 256, (KV_LEN + 127) / 128), 256, GB_SMEM>>>(
        cross_hi, cross_lo,
        wqkvT_hi + (size_t)(NH * HD) * HIDDEN, wqkvT_lo + (size_t)(NH * HD) * HIDDEN,
        pkv, KV_LEN, KV_N);
    // 5) Q projection: M=1024, N=4096 (grid 16 x 8)
    gemm_bf16x3<<<dim3(HIDDEN / 256, Q_LEN / 128), 256, GB_SMEM>>>(
        hid_hi, hid_lo, wqkvT_hi, wqkvT_lo, pq, Q_LEN, HIDDEN);

    // 6,7) RMS norms -> bf16 hi/lo
    {
        int nwarps = Q_LEN * NH;
        rmsnorm_split<<<(nwarps * 32 + 255) / 256, 256>>>(
            pq, q_norm, qhi, qlo, Q_LEN, NH, HIDDEN, HIDDEN);
        nwarps = KV_LEN * NKVH;
        rmsnorm_split<<<(nwarps * 32 + 255) / 256, 256>>>(
            pkv, k_norm, khi, klo, KV_LEN, NKVH, KV_N, NKVH * HD);
    }
    // 8) V transpose + split
    vtrans_split<<<dim3(KV_PAD / 32, HD / 32, NKVH), dim3(32, 8)>>>(pkv);

    // 9) attention
    cudaFuncSetAttribute(attn_mma, cudaFuncAttributeMaxDynamicSharedMemorySize,
                         ATTN_SMEM);
    attn_mma<<<dim3(Q_LEN / 128, NH), 256, ATTN_SMEM>>>(mask);

    // 10) O projection: M=1024, N=4096
    gemm_bf16x3<<<dim3(HIDDEN / 256, Q_LEN / 128), 256, GB_SMEM>>>(
        attnhi, attnlo, woT_hi, woT_lo, out, Q_LEN, HIDDEN);
}